// round 2
// baseline (speedup 1.0000x reference)
#include <cuda_runtime.h>
#include <cstdint>

// Problem constants (fixed by the dataset)
#define F_IN   256
#define F_OUT  128
#define MAX_NODES 100000

// Static scratch for h = x @ W  (51.2 MB) — __device__ global, no allocation.
__device__ float g_h[(size_t)MAX_NODES * F_OUT];

// ---------------------------------------------------------------------------
// Kernel 1: out[i][f] = bias[f]   (d_out is poisoned; must init)
// ---------------------------------------------------------------------------
__global__ void init_out_kernel(const float* __restrict__ bias,
                                float* __restrict__ out, int n_nodes) {
    long long idx = (long long)blockIdx.x * blockDim.x + threadIdx.x;
    long long total4 = (long long)n_nodes * (F_OUT / 4);
    if (idx >= total4) return;
    int f4 = (int)(idx % (F_OUT / 4));
    const float4 b = ((const float4*)bias)[f4];
    ((float4*)out)[idx] = b;
}

// ---------------------------------------------------------------------------
// Kernel 2: tiled SGEMM  h[M,128] = x[M,256] @ W[256,128]
// BM=128, BN=128, BK=16, 256 threads, 8x8 micro-tile per thread.
// ---------------------------------------------------------------------------
#define BM 128
#define BN 128
#define BK 16
#define TM 8
#define TN 8

__global__ __launch_bounds__(256, 2)
void gemm_kernel(const float* __restrict__ x, const float* __restrict__ w,
                 float* __restrict__ h, int M) {
    __shared__ float As[BK][BM];   // A transposed: As[k][m]
    __shared__ float Bs[BK][BN];

    const int tid = threadIdx.x;
    const int block_row = blockIdx.x * BM;
    const int tr = tid / 16;       // 0..15
    const int tc = tid % 16;       // 0..15

    float acc[TM][TN];
    #pragma unroll
    for (int i = 0; i < TM; i++)
        #pragma unroll
        for (int j = 0; j < TN; j++) acc[i][j] = 0.0f;

    for (int k0 = 0; k0 < F_IN; k0 += BK) {
        // Load A tile: 128 rows x 16 cols = 512 float4; 2 per thread.
        #pragma unroll
        for (int i = 0; i < 2; i++) {
            int idx = tid + i * 256;       // 0..511
            int row = idx >> 2;            // 4 float4 per row
            int c4  = idx & 3;
            int grow = block_row + row;
            float4 v = make_float4(0.f, 0.f, 0.f, 0.f);
            if (grow < M)
                v = *(const float4*)&x[(long long)grow * F_IN + k0 + c4 * 4];
            As[c4 * 4 + 0][row] = v.x;
            As[c4 * 4 + 1][row] = v.y;
            As[c4 * 4 + 2][row] = v.z;
            As[c4 * 4 + 3][row] = v.w;
        }
        // Load B tile: 16 rows x 128 cols = 512 float4; 2 per thread.
        #pragma unroll
        for (int i = 0; i < 2; i++) {
            int idx = tid + i * 256;
            int row = idx >> 5;            // 32 float4 per row
            int c4  = idx & 31;
            *(float4*)&Bs[row][c4 * 4] =
                *(const float4*)&w[(long long)(k0 + row) * F_OUT + c4 * 4];
        }
        __syncthreads();

        #pragma unroll
        for (int kk = 0; kk < BK; kk++) {
            float a[TM], b[TN];
            #pragma unroll
            for (int i = 0; i < TM; i += 4)
                *(float4*)&a[i] = *(const float4*)&As[kk][tr * TM + i];
            #pragma unroll
            for (int j = 0; j < TN; j += 4)
                *(float4*)&b[j] = *(const float4*)&Bs[kk][tc * TN + j];
            #pragma unroll
            for (int i = 0; i < TM; i++)
                #pragma unroll
                for (int j = 0; j < TN; j++)
                    acc[i][j] += a[i] * b[j];
        }
        __syncthreads();
    }

    // Write back h
    #pragma unroll
    for (int i = 0; i < TM; i++) {
        int grow = block_row + tr * TM + i;
        if (grow < M) {
            #pragma unroll
            for (int j = 0; j < TN; j += 4) {
                *(float4*)&h[(long long)grow * F_OUT + tc * TN + j] =
                    *(const float4*)&acc[i][j];
            }
        }
    }
}

// ---------------------------------------------------------------------------
// Kernel 3: edge scatter.  One warp handles EDGES_PER_WARP edges.
// Lanes 0..3 coalesce-load the 4 edges' (src,dst,val); broadcast by shfl.
// Per edge: 32 lanes each gather one float4 of h[src], scale by val,
// and issue red.global.add.v4.f32 into out[dst].
// Edge indices are INT32 (jax default x64-disabled downcasts int64).
// ---------------------------------------------------------------------------
#define EDGES_PER_WARP 4

__global__ __launch_bounds__(256)
void scatter_kernel(const int* __restrict__ edge_src,
                    const int* __restrict__ edge_dst,
                    const float* __restrict__ edge_vals,
                    const float* __restrict__ h,
                    float* __restrict__ out, int E) {
    const int warp_id = (blockIdx.x * blockDim.x + threadIdx.x) >> 5;
    const int lane = threadIdx.x & 31;
    const long long e0 = (long long)warp_id * EDGES_PER_WARP;

    int my_s = 0, my_d = 0;
    float my_v = 0.0f;
    if (lane < EDGES_PER_WARP && e0 + lane < E) {
        my_s = edge_src[e0 + lane];
        my_d = edge_dst[e0 + lane];
        my_v = edge_vals[e0 + lane];
    }

    #pragma unroll
    for (int k = 0; k < EDGES_PER_WARP; k++) {
        if (e0 + k >= E) return;
        int   s = __shfl_sync(0xFFFFFFFFu, my_s, k);
        int   d = __shfl_sync(0xFFFFFFFFu, my_d, k);
        float v = __shfl_sync(0xFFFFFFFFu, my_v, k);

        float4 m = ((const float4*)(h + (long long)s * F_OUT))[lane];
        m.x *= v; m.y *= v; m.z *= v; m.w *= v;

        float* op = out + (long long)d * F_OUT + lane * 4;
        asm volatile("red.global.add.v4.f32 [%0], {%1, %2, %3, %4};"
                     :: "l"(op), "f"(m.x), "f"(m.y), "f"(m.z), "f"(m.w)
                     : "memory");
    }
}

// ---------------------------------------------------------------------------
// Launch
// Inputs (metadata order): x[f32], edge_src[i32], edge_dst[i32],
//                          edge_vals[f32], kernel[f32], bias[f32]
// ---------------------------------------------------------------------------
extern "C" void kernel_launch(void* const* d_in, const int* in_sizes, int n_in,
                              void* d_out, int out_size) {
    const float* x    = (const float*)d_in[0];
    const int*   esrc = (const int*)d_in[1];
    const int*   edst = (const int*)d_in[2];
    const float* eval = (const float*)d_in[3];
    const float* w    = (const float*)d_in[4];
    const float* bias = (const float*)d_in[5];
    float*       out  = (float*)d_out;

    const int M = in_sizes[0] / F_IN;     // 100000 nodes
    const int E = in_sizes[1];            // 1.6M edges

    float* h;
    cudaGetSymbolAddress((void**)&h, g_h);

    // 1) out = bias (broadcast)
    {
        long long total4 = (long long)M * (F_OUT / 4);
        int threads = 256;
        int blocks = (int)((total4 + threads - 1) / threads);
        init_out_kernel<<<blocks, threads>>>(bias, out, M);
    }
    // 2) h = x @ W
    {
        int blocks = (M + BM - 1) / BM;   // 782
        gemm_kernel<<<blocks, 256>>>(x, w, h, M);
    }
    // 3) scatter-aggregate
    {
        long long warps = ((long long)E + EDGES_PER_WARP - 1) / EDGES_PER_WARP;
        int threads = 256;                // 8 warps/block
        int blocks = (int)((warps * 32 + threads - 1) / threads);
        scatter_kernel<<<blocks, threads>>>(esrc, edst, eval, h, out, E);
    }
}

// round 4
// speedup vs baseline: 1.1767x; 1.1767x over previous
#include <cuda_runtime.h>
#include <cstdint>

#define F_IN   256
#define F_OUT  128

// Static scratch — __device__ globals (no allocation allowed).
__device__ float g_h[(size_t)100000 * F_OUT];     // h = x @ W   (51.2 MB)
__device__ float g_Bh[F_IN * F_OUT];              // W^T hi (tf32 bits), [n][k]
__device__ float g_Bl[F_IN * F_OUT];              // W^T lo (tf32 bits), [n][k]

__device__ __forceinline__ float to_tf32(float a) {
    uint32_t r;
    asm("cvt.rna.tf32.f32 %0, %1;" : "=r"(r) : "f"(a));
    return __uint_as_float(r);
}

// ---------------------------------------------------------------------------
// Kernel 1: out[i][f] = bias[f]
// ---------------------------------------------------------------------------
__global__ void init_out_kernel(const float* __restrict__ bias,
                                float* __restrict__ out, int n_nodes) {
    long long idx = (long long)blockIdx.x * blockDim.x + threadIdx.x;
    long long total4 = (long long)n_nodes * (F_OUT / 4);
    if (idx >= total4) return;
    int f4 = (int)(idx % (F_OUT / 4));
    const float4 b = ((const float4*)bias)[f4];
    ((float4*)out)[idx] = b;
}

// ---------------------------------------------------------------------------
// Kernel 2a: W transpose + tf32 hi/lo split:  Bh[n][k]=tf32(w[k][n]), Bl=resid
// ---------------------------------------------------------------------------
__global__ void wsplit_kernel(const float* __restrict__ w,
                              float* __restrict__ bh, float* __restrict__ bl) {
    int k = blockIdx.x;        // 0..255
    int n = threadIdx.x;       // 0..127
    float a = w[k * F_OUT + n];
    float hi = to_tf32(a);
    bh[n * F_IN + k] = hi;
    bl[n * F_IN + k] = to_tf32(a - hi);
}

// ---------------------------------------------------------------------------
// Kernel 2b: mma.sync tf32 GEMM (3xTF32):  h[M,128] = x[M,256] @ W
// CTA 128x128, 8 warps (4 m x 2 n), warp tile 32x64.
// K chunks of 32. SMEM stride 36 -> conflict-free fragment loads.
// ---------------------------------------------------------------------------
#define KC       32
#define NCHUNK   (F_IN / KC)       // 8
#define AS       36                // padded row stride (floats)
#define SM_AH    0
#define SM_AL    (128 * AS)
#define SM_BH    (2 * 128 * AS)
#define SM_BL    (3 * 128 * AS)
#define GEMM_SMEM_BYTES (4 * 128 * AS * 4)   // 73728

__device__ __forceinline__ void mma_tf32_sync(float* d, const uint32_t* a,
                                              const uint32_t* b) {
    asm volatile(
        "mma.sync.aligned.m16n8k8.row.col.f32.tf32.tf32.f32 "
        "{%0, %1, %2, %3}, {%4, %5, %6, %7}, {%8, %9}, {%0, %1, %2, %3};"
        : "+f"(d[0]), "+f"(d[1]), "+f"(d[2]), "+f"(d[3])
        : "r"(a[0]), "r"(a[1]), "r"(a[2]), "r"(a[3]), "r"(b[0]), "r"(b[1]));
}

__global__ __launch_bounds__(256, 2)
void gemm_mma_kernel(const float* __restrict__ x,
                     const float* __restrict__ bh_g,
                     const float* __restrict__ bl_g,
                     float* __restrict__ h, int M) {
    extern __shared__ float sm[];
    const int tid  = threadIdx.x;
    const int wid  = tid >> 5;
    const int lane = tid & 31;
    const int g = lane >> 2;       // group (row within 8)
    const int t = lane & 3;        // tid-in-group (col within 4)
    const int wm = wid & 3;        // warp m index (0..3) -> rows wm*32
    const int wn = wid >> 2;       // warp n index (0..1) -> cols wn*64
    const int block_row = blockIdx.x * 128;

    float acc[2][8][4];
    #pragma unroll
    for (int i = 0; i < 2; i++)
        #pragma unroll
        for (int j = 0; j < 8; j++)
            #pragma unroll
            for (int q = 0; q < 4; q++) acc[i][j][q] = 0.0f;

    for (int c = 0; c < NCHUNK; c++) {
        if (c > 0) __syncthreads();
        // ---- A: 128 rows x 32 cols; fp32 -> tf32 hi/lo split ----
        #pragma unroll
        for (int i = 0; i < 4; i++) {
            int fidx = i * 256 + tid;          // 0..1023 float4 slots
            int row = fidx >> 3, c4 = fidx & 7;
            int grow = block_row + row;
            float4 v = make_float4(0.f, 0.f, 0.f, 0.f);
            if (grow < M)
                v = *(const float4*)(x + (size_t)grow * F_IN + c * KC + c4 * 4);
            float4 hi, lo;
            hi.x = to_tf32(v.x); hi.y = to_tf32(v.y);
            hi.z = to_tf32(v.z); hi.w = to_tf32(v.w);
            lo.x = to_tf32(v.x - hi.x); lo.y = to_tf32(v.y - hi.y);
            lo.z = to_tf32(v.z - hi.z); lo.w = to_tf32(v.w - hi.w);
            *(float4*)(sm + SM_AH + row * AS + c4 * 4) = hi;
            *(float4*)(sm + SM_AL + row * AS + c4 * 4) = lo;
        }
        // ---- B: 128 n-rows x 32 k-cols (pre-split in gmem) ----
        #pragma unroll
        for (int i = 0; i < 4; i++) {
            int fidx = i * 256 + tid;
            int row = fidx >> 3, c4 = fidx & 7;
            float4 vh = *(const float4*)(bh_g + (size_t)row * F_IN + c * KC + c4 * 4);
            float4 vl = *(const float4*)(bl_g + (size_t)row * F_IN + c * KC + c4 * 4);
            *(float4*)(sm + SM_BH + row * AS + c4 * 4) = vh;
            *(float4*)(sm + SM_BL + row * AS + c4 * 4) = vl;
        }
        __syncthreads();

        #pragma unroll
        for (int k0 = 0; k0 < KC; k0 += 8) {
            // A fragments for this warp's two 16-row tiles
            uint32_t ah[2][4], al[2][4];
            #pragma unroll
            for (int mt = 0; mt < 2; mt++) {
                int r0 = (wm * 32 + mt * 16 + g) * AS + k0 + t;
                int r8 = (wm * 32 + mt * 16 + g + 8) * AS + k0 + t;
                ah[mt][0] = __float_as_uint(sm[SM_AH + r0]);
                ah[mt][1] = __float_as_uint(sm[SM_AH + r8]);
                ah[mt][2] = __float_as_uint(sm[SM_AH + r0 + 4]);
                ah[mt][3] = __float_as_uint(sm[SM_AH + r8 + 4]);
                al[mt][0] = __float_as_uint(sm[SM_AL + r0]);
                al[mt][1] = __float_as_uint(sm[SM_AL + r8]);
                al[mt][2] = __float_as_uint(sm[SM_AL + r0 + 4]);
                al[mt][3] = __float_as_uint(sm[SM_AL + r8 + 4]);
            }
            #pragma unroll
            for (int nt = 0; nt < 8; nt++) {
                int nrow = (wn * 64 + nt * 8 + g) * AS + k0 + t;
                uint32_t bh[2], bl[2];
                bh[0] = __float_as_uint(sm[SM_BH + nrow]);
                bh[1] = __float_as_uint(sm[SM_BH + nrow + 4]);
                bl[0] = __float_as_uint(sm[SM_BL + nrow]);
                bl[1] = __float_as_uint(sm[SM_BL + nrow + 4]);
                #pragma unroll
                for (int mt = 0; mt < 2; mt++) {
                    mma_tf32_sync(acc[mt][nt], ah[mt], bh);
                    mma_tf32_sync(acc[mt][nt], al[mt], bh);
                    mma_tf32_sync(acc[mt][nt], ah[mt], bl);
                }
            }
        }
    }

    // ---- writeback: D[g][2t],[g][2t+1] and [g+8][...] per (mt, nt) ----
    #pragma unroll
    for (int mt = 0; mt < 2; mt++) {
        int row0 = block_row + wm * 32 + mt * 16 + g;
        int row8 = row0 + 8;
        #pragma unroll
        for (int nt = 0; nt < 8; nt++) {
            int col = wn * 64 + nt * 8 + 2 * t;
            if (row0 < M)
                *(float2*)(h + (size_t)row0 * F_OUT + col) =
                    make_float2(acc[mt][nt][0], acc[mt][nt][1]);
            if (row8 < M)
                *(float2*)(h + (size_t)row8 * F_OUT + col) =
                    make_float2(acc[mt][nt][2], acc[mt][nt][3]);
        }
    }
}

// ---------------------------------------------------------------------------
// Kernel 3: edge scatter (unchanged from passing R2 version).
// ---------------------------------------------------------------------------
#define EDGES_PER_WARP 4

__global__ __launch_bounds__(256)
void scatter_kernel(const int* __restrict__ edge_src,
                    const int* __restrict__ edge_dst,
                    const float* __restrict__ edge_vals,
                    const float* __restrict__ h,
                    float* __restrict__ out, int E) {
    const int warp_id = (blockIdx.x * blockDim.x + threadIdx.x) >> 5;
    const int lane = threadIdx.x & 31;
    const long long e0 = (long long)warp_id * EDGES_PER_WARP;

    int my_s = 0, my_d = 0;
    float my_v = 0.0f;
    if (lane < EDGES_PER_WARP && e0 + lane < E) {
        my_s = edge_src[e0 + lane];
        my_d = edge_dst[e0 + lane];
        my_v = edge_vals[e0 + lane];
    }

    #pragma unroll
    for (int k = 0; k < EDGES_PER_WARP; k++) {
        if (e0 + k >= E) return;
        int   s = __shfl_sync(0xFFFFFFFFu, my_s, k);
        int   d = __shfl_sync(0xFFFFFFFFu, my_d, k);
        float v = __shfl_sync(0xFFFFFFFFu, my_v, k);

        float4 m = ((const float4*)(h + (long long)s * F_OUT))[lane];
        m.x *= v; m.y *= v; m.z *= v; m.w *= v;

        float* op = out + (long long)d * F_OUT + lane * 4;
        asm volatile("red.global.add.v4.f32 [%0], {%1, %2, %3, %4};"
                     :: "l"(op), "f"(m.x), "f"(m.y), "f"(m.z), "f"(m.w)
                     : "memory");
    }
}

// ---------------------------------------------------------------------------
// Launch.  Inputs: x[f32], edge_src[i32], edge_dst[i32], edge_vals[f32],
//                  kernel[f32], bias[f32]
// ---------------------------------------------------------------------------
extern "C" void kernel_launch(void* const* d_in, const int* in_sizes, int n_in,
                              void* d_out, int out_size) {
    const float* x    = (const float*)d_in[0];
    const int*   esrc = (const int*)d_in[1];
    const int*   edst = (const int*)d_in[2];
    const float* eval = (const float*)d_in[3];
    const float* w    = (const float*)d_in[4];
    const float* bias = (const float*)d_in[5];
    float*       out  = (float*)d_out;

    const int M = in_sizes[0] / F_IN;     // 100000
    const int E = in_sizes[1];            // 1.6M

    float *h, *bh, *bl;
    cudaGetSymbolAddress((void**)&h,  g_h);
    cudaGetSymbolAddress((void**)&bh, g_Bh);
    cudaGetSymbolAddress((void**)&bl, g_Bl);

    // 1) out = bias
    {
        long long total4 = (long long)M * (F_OUT / 4);
        int threads = 256;
        int blocks = (int)((total4 + threads - 1) / threads);
        init_out_kernel<<<blocks, threads>>>(bias, out, M);
    }
    // 2a) W transpose + tf32 hi/lo split
    wsplit_kernel<<<F_IN, F_OUT>>>(w, bh, bl);
    // 2b) h = x @ W via mma.sync tf32 (3xTF32)
    {
        static int smem_set = 0;
        if (!smem_set) {
            cudaFuncSetAttribute(gemm_mma_kernel,
                                 cudaFuncAttributeMaxDynamicSharedMemorySize,
                                 GEMM_SMEM_BYTES);
            smem_set = 1;
        }
        int blocks = (M + 127) / 128;     // 782
        gemm_mma_kernel<<<blocks, 256, GEMM_SMEM_BYTES>>>(x, bh, bl, h, M);
    }
    // 3) scatter-aggregate
    {
        long long warps = ((long long)E + EDGES_PER_WARP - 1) / EDGES_PER_WARP;
        int threads = 256;
        int blocks = (int)((warps * 32 + threads - 1) / threads);
        scatter_kernel<<<blocks, threads>>>(esrc, edst, eval, h, out, E);
    }
}

// round 5
// speedup vs baseline: 1.2822x; 1.0897x over previous
#include <cuda_runtime.h>
#include <cstdint>

#define F_IN     256
#define F_OUT    128
#define MAX_N    100352            // 98 * 1024, covers 100000
#define MAX_E    1600000
#define SCAN_BLK 1024

// Static scratch — __device__ globals (no allocation allowed).
__device__ float g_h[(size_t)100000 * F_OUT];   // h = x @ W (51.2 MB)
__device__ float g_Bh[F_IN * F_OUT];            // W^T hi (tf32), [n][k]
__device__ float g_Bl[F_IN * F_OUT];            // W^T lo (tf32), [n][k]
__device__ int   g_cnt[MAX_N];                  // per-dst degree
__device__ int   g_scan[MAX_N];                 // block-local exclusive scan
__device__ int   g_bsum[256];                   // per-block sums (<=98 used)
__device__ int   g_off[MAX_N + 1];              // CSR offsets
__device__ int   g_cur[MAX_N];                  // fill cursors
__device__ int   g_eidx[MAX_E];                 // edge ids grouped by dst

__device__ __forceinline__ float to_tf32(float a) {
    uint32_t r;
    asm("cvt.rna.tf32.f32 %0, %1;" : "=r"(r) : "f"(a));
    return __uint_as_float(r);
}

// ---------------------------------------------------------------------------
// CSR build: count -> scanA -> scanB -> scanC -> fill
// ---------------------------------------------------------------------------
__global__ void zero_cnt_kernel(int n_pad) {
    int i = blockIdx.x * blockDim.x + threadIdx.x;
    if (i < n_pad) g_cnt[i] = 0;
}

__global__ void count_kernel(const int* __restrict__ edge_dst, int E) {
    int i = blockIdx.x * blockDim.x + threadIdx.x;
    if (i < E) atomicAdd(&g_cnt[edge_dst[i]], 1);
}

// Block-level exclusive scan of g_cnt (1024 elems/block), block sums to g_bsum.
__global__ __launch_bounds__(SCAN_BLK)
void scanA_kernel() {
    __shared__ int s[SCAN_BLK];
    int t = threadIdx.x;
    int i = blockIdx.x * SCAN_BLK + t;
    int v = g_cnt[i];
    s[t] = v;
    __syncthreads();
    #pragma unroll
    for (int off = 1; off < SCAN_BLK; off <<= 1) {
        int tmp = (t >= off) ? s[t - off] : 0;
        __syncthreads();
        s[t] += tmp;
        __syncthreads();
    }
    g_scan[i] = s[t] - v;                       // exclusive
    if (t == SCAN_BLK - 1) g_bsum[blockIdx.x] = s[t];
}

// Single-block exclusive scan of g_bsum[nblk].
__global__ __launch_bounds__(256)
void scanB_kernel(int nblk) {
    __shared__ int s[256];
    int t = threadIdx.x;
    int v = (t < nblk) ? g_bsum[t] : 0;
    s[t] = v;
    __syncthreads();
    #pragma unroll
    for (int off = 1; off < 256; off <<= 1) {
        int tmp = (t >= off) ? s[t - off] : 0;
        __syncthreads();
        s[t] += tmp;
        __syncthreads();
    }
    g_bsum[t] = s[t] - v;                       // exclusive
}

__global__ void scanC_kernel(int N, int E) {
    int i = blockIdx.x * blockDim.x + threadIdx.x;
    if (i <= N) {
        int o = (i == N) ? E : (g_scan[i] + g_bsum[i / SCAN_BLK]);
        g_off[i] = o;
        if (i < N) g_cur[i] = o;
    }
}

__global__ void fill_kernel(const int* __restrict__ edge_dst, int E) {
    int i = blockIdx.x * blockDim.x + threadIdx.x;
    if (i < E) {
        int p = atomicAdd(&g_cur[edge_dst[i]], 1);
        g_eidx[p] = i;
    }
}

// ---------------------------------------------------------------------------
// Kernel 2a: W transpose + tf32 hi/lo split
// ---------------------------------------------------------------------------
__global__ void wsplit_kernel(const float* __restrict__ w,
                              float* __restrict__ bh, float* __restrict__ bl) {
    int k = blockIdx.x;        // 0..255
    int n = threadIdx.x;       // 0..127
    float a = w[k * F_OUT + n];
    float hi = to_tf32(a);
    bh[n * F_IN + k] = hi;
    bl[n * F_IN + k] = to_tf32(a - hi);
}

// ---------------------------------------------------------------------------
// Kernel 2b: mma.sync tf32 GEMM (3xTF32) — unchanged from passing R4.
// ---------------------------------------------------------------------------
#define KC       32
#define NCHUNK   (F_IN / KC)       // 8
#define AS       36
#define SM_AH    0
#define SM_AL    (128 * AS)
#define SM_BH    (2 * 128 * AS)
#define SM_BL    (3 * 128 * AS)
#define GEMM_SMEM_BYTES (4 * 128 * AS * 4)   // 73728

__device__ __forceinline__ void mma_tf32_sync(float* d, const uint32_t* a,
                                              const uint32_t* b) {
    asm volatile(
        "mma.sync.aligned.m16n8k8.row.col.f32.tf32.tf32.f32 "
        "{%0, %1, %2, %3}, {%4, %5, %6, %7}, {%8, %9}, {%0, %1, %2, %3};"
        : "+f"(d[0]), "+f"(d[1]), "+f"(d[2]), "+f"(d[3])
        : "r"(a[0]), "r"(a[1]), "r"(a[2]), "r"(a[3]), "r"(b[0]), "r"(b[1]));
}

__global__ __launch_bounds__(256, 2)
void gemm_mma_kernel(const float* __restrict__ x,
                     const float* __restrict__ bh_g,
                     const float* __restrict__ bl_g,
                     float* __restrict__ h, int M) {
    extern __shared__ float sm[];
    const int tid  = threadIdx.x;
    const int wid  = tid >> 5;
    const int lane = tid & 31;
    const int g = lane >> 2;
    const int t = lane & 3;
    const int wm = wid & 3;
    const int wn = wid >> 2;
    const int block_row = blockIdx.x * 128;

    float acc[2][8][4];
    #pragma unroll
    for (int i = 0; i < 2; i++)
        #pragma unroll
        for (int j = 0; j < 8; j++)
            #pragma unroll
            for (int q = 0; q < 4; q++) acc[i][j][q] = 0.0f;

    for (int c = 0; c < NCHUNK; c++) {
        if (c > 0) __syncthreads();
        #pragma unroll
        for (int i = 0; i < 4; i++) {
            int fidx = i * 256 + tid;
            int row = fidx >> 3, c4 = fidx & 7;
            int grow = block_row + row;
            float4 v = make_float4(0.f, 0.f, 0.f, 0.f);
            if (grow < M)
                v = *(const float4*)(x + (size_t)grow * F_IN + c * KC + c4 * 4);
            float4 hi, lo;
            hi.x = to_tf32(v.x); hi.y = to_tf32(v.y);
            hi.z = to_tf32(v.z); hi.w = to_tf32(v.w);
            lo.x = to_tf32(v.x - hi.x); lo.y = to_tf32(v.y - hi.y);
            lo.z = to_tf32(v.z - hi.z); lo.w = to_tf32(v.w - hi.w);
            *(float4*)(sm + SM_AH + row * AS + c4 * 4) = hi;
            *(float4*)(sm + SM_AL + row * AS + c4 * 4) = lo;
        }
        #pragma unroll
        for (int i = 0; i < 4; i++) {
            int fidx = i * 256 + tid;
            int row = fidx >> 3, c4 = fidx & 7;
            float4 vh = *(const float4*)(bh_g + (size_t)row * F_IN + c * KC + c4 * 4);
            float4 vl = *(const float4*)(bl_g + (size_t)row * F_IN + c * KC + c4 * 4);
            *(float4*)(sm + SM_BH + row * AS + c4 * 4) = vh;
            *(float4*)(sm + SM_BL + row * AS + c4 * 4) = vl;
        }
        __syncthreads();

        #pragma unroll
        for (int k0 = 0; k0 < KC; k0 += 8) {
            uint32_t ah[2][4], al[2][4];
            #pragma unroll
            for (int mt = 0; mt < 2; mt++) {
                int r0 = (wm * 32 + mt * 16 + g) * AS + k0 + t;
                int r8 = (wm * 32 + mt * 16 + g + 8) * AS + k0 + t;
                ah[mt][0] = __float_as_uint(sm[SM_AH + r0]);
                ah[mt][1] = __float_as_uint(sm[SM_AH + r8]);
                ah[mt][2] = __float_as_uint(sm[SM_AH + r0 + 4]);
                ah[mt][3] = __float_as_uint(sm[SM_AH + r8 + 4]);
                al[mt][0] = __float_as_uint(sm[SM_AL + r0]);
                al[mt][1] = __float_as_uint(sm[SM_AL + r8]);
                al[mt][2] = __float_as_uint(sm[SM_AL + r0 + 4]);
                al[mt][3] = __float_as_uint(sm[SM_AL + r8 + 4]);
            }
            #pragma unroll
            for (int nt = 0; nt < 8; nt++) {
                int nrow = (wn * 64 + nt * 8 + g) * AS + k0 + t;
                uint32_t bh[2], bl[2];
                bh[0] = __float_as_uint(sm[SM_BH + nrow]);
                bh[1] = __float_as_uint(sm[SM_BH + nrow + 4]);
                bl[0] = __float_as_uint(sm[SM_BL + nrow]);
                bl[1] = __float_as_uint(sm[SM_BL + nrow + 4]);
                #pragma unroll
                for (int mt = 0; mt < 2; mt++) {
                    mma_tf32_sync(acc[mt][nt], ah[mt], bh);
                    mma_tf32_sync(acc[mt][nt], al[mt], bh);
                    mma_tf32_sync(acc[mt][nt], ah[mt], bl);
                }
            }
        }
    }

    #pragma unroll
    for (int mt = 0; mt < 2; mt++) {
        int row0 = block_row + wm * 32 + mt * 16 + g;
        int row8 = row0 + 8;
        #pragma unroll
        for (int nt = 0; nt < 8; nt++) {
            int col = wn * 64 + nt * 8 + 2 * t;
            if (row0 < M)
                *(float2*)(h + (size_t)row0 * F_OUT + col) =
                    make_float2(acc[mt][nt][0], acc[mt][nt][1]);
            if (row8 < M)
                *(float2*)(h + (size_t)row8 * F_OUT + col) =
                    make_float2(acc[mt][nt][2], acc[mt][nt][3]);
        }
    }
}

// ---------------------------------------------------------------------------
// Kernel 3: CSR aggregation. One warp per dst node; register accumulation;
// folds bias; writes every node (no init kernel, no float atomics).
// ---------------------------------------------------------------------------
__global__ __launch_bounds__(256)
void aggregate_kernel(const int* __restrict__ esrc,
                      const float* __restrict__ eval,
                      const float* __restrict__ h,
                      const float* __restrict__ bias,
                      float* __restrict__ out, int N) {
    const int warp = (blockIdx.x * blockDim.x + threadIdx.x) >> 5;
    const int lane = threadIdx.x & 31;
    if (warp >= N) return;

    const int s0 = g_off[warp];
    const int s1 = g_off[warp + 1];
    float4 acc = ((const float4*)bias)[lane];

    for (int base = s0; base < s1; base += 32) {
        int s = 0; float v = 0.0f;
        if (base + lane < s1) {
            int e = g_eidx[base + lane];
            s = esrc[e];
            v = eval[e];
        }
        const int cnt = min(32, s1 - base);
        for (int j = 0; j < cnt; j++) {
            int   ss = __shfl_sync(0xFFFFFFFFu, s, j);
            float vv = __shfl_sync(0xFFFFFFFFu, v, j);
            float4 m = ((const float4*)(h + (size_t)ss * F_OUT))[lane];
            acc.x += m.x * vv; acc.y += m.y * vv;
            acc.z += m.z * vv; acc.w += m.w * vv;
        }
    }
    ((float4*)(out + (size_t)warp * F_OUT))[lane] = acc;
}

// ---------------------------------------------------------------------------
// Launch.  Inputs: x[f32], edge_src[i32], edge_dst[i32], edge_vals[f32],
//                  kernel[f32], bias[f32]
// ---------------------------------------------------------------------------
extern "C" void kernel_launch(void* const* d_in, const int* in_sizes, int n_in,
                              void* d_out, int out_size) {
    const float* x    = (const float*)d_in[0];
    const int*   esrc = (const int*)d_in[1];
    const int*   edst = (const int*)d_in[2];
    const float* eval = (const float*)d_in[3];
    const float* w    = (const float*)d_in[4];
    const float* bias = (const float*)d_in[5];
    float*       out  = (float*)d_out;

    const int M = in_sizes[0] / F_IN;     // 100000 nodes
    const int E = in_sizes[1];            // 1.6M edges
    const int n_pad  = ((M + SCAN_BLK - 1) / SCAN_BLK) * SCAN_BLK;
    const int n_sblk = n_pad / SCAN_BLK;  // 98

    float *h, *bh, *bl;
    cudaGetSymbolAddress((void**)&h,  g_h);
    cudaGetSymbolAddress((void**)&bh, g_Bh);
    cudaGetSymbolAddress((void**)&bl, g_Bl);

    // --- CSR build ---
    zero_cnt_kernel<<<(n_pad + 255) / 256, 256>>>(n_pad);
    count_kernel<<<(E + 255) / 256, 256>>>(edst, E);
    scanA_kernel<<<n_sblk, SCAN_BLK>>>();
    scanB_kernel<<<1, 256>>>(n_sblk);
    scanC_kernel<<<(M + 256) / 256, 256>>>(M, E);
    fill_kernel<<<(E + 255) / 256, 256>>>(edst, E);

    // --- h = x @ W (3xTF32 mma.sync) ---
    wsplit_kernel<<<F_IN, F_OUT>>>(w, bh, bl);
    {
        static int smem_set = 0;
        if (!smem_set) {
            cudaFuncSetAttribute(gemm_mma_kernel,
                                 cudaFuncAttributeMaxDynamicSharedMemorySize,
                                 GEMM_SMEM_BYTES);
            smem_set = 1;
        }
        int blocks = (M + 127) / 128;
        gemm_mma_kernel<<<blocks, 256, GEMM_SMEM_BYTES>>>(x, bh, bl, h, M);
    }

    // --- out = segment_sum + bias (warp per node) ---
    {
        int blocks = (M * 32 + 255) / 256;   // 12500
        aggregate_kernel<<<blocks, 256>>>(esrc, eval, h, bias, out, M);
    }
}

// round 6
// speedup vs baseline: 1.6180x; 1.2619x over previous
#include <cuda_runtime.h>
#include <cuda_bf16.h>
#include <cstdint>

#define F_IN     256
#define F_OUT    128
#define MAX_N    100352            // 98 * 1024, covers 100000
#define MAX_E    1600000
#define SCAN_BLK 1024

// Static scratch — __device__ globals (no allocation allowed).
__device__ float g_h[(size_t)100000 * F_OUT];        // h = x @ W (51.2 MB)
__device__ __nv_bfloat16 g_Bh16[F_IN * F_OUT];       // W^T hi bf16, [n][k]
__device__ __nv_bfloat16 g_Bl16[F_IN * F_OUT];       // W^T lo bf16, [n][k]
__device__ int   g_cnt[MAX_N];
__device__ int   g_scan[MAX_N];
__device__ int   g_bsum[256];
__device__ int   g_off[MAX_N + 1];
__device__ int   g_cur[MAX_N];
__device__ int   g_eidx[MAX_E];

// ---------------------------------------------------------------------------
// CSR build: count -> scanA -> scanB -> scanC -> fill  (unchanged, passing)
// ---------------------------------------------------------------------------
__global__ void zero_cnt_kernel(int n_pad) {
    int i = blockIdx.x * blockDim.x + threadIdx.x;
    if (i < n_pad) g_cnt[i] = 0;
}

__global__ void count_kernel(const int* __restrict__ edge_dst, int E) {
    int i = blockIdx.x * blockDim.x + threadIdx.x;
    if (i < E) atomicAdd(&g_cnt[edge_dst[i]], 1);
}

__global__ __launch_bounds__(SCAN_BLK)
void scanA_kernel() {
    __shared__ int s[SCAN_BLK];
    int t = threadIdx.x;
    int i = blockIdx.x * SCAN_BLK + t;
    int v = g_cnt[i];
    s[t] = v;
    __syncthreads();
    #pragma unroll
    for (int off = 1; off < SCAN_BLK; off <<= 1) {
        int tmp = (t >= off) ? s[t - off] : 0;
        __syncthreads();
        s[t] += tmp;
        __syncthreads();
    }
    g_scan[i] = s[t] - v;
    if (t == SCAN_BLK - 1) g_bsum[blockIdx.x] = s[t];
}

__global__ __launch_bounds__(256)
void scanB_kernel(int nblk) {
    __shared__ int s[256];
    int t = threadIdx.x;
    int v = (t < nblk) ? g_bsum[t] : 0;
    s[t] = v;
    __syncthreads();
    #pragma unroll
    for (int off = 1; off < 256; off <<= 1) {
        int tmp = (t >= off) ? s[t - off] : 0;
        __syncthreads();
        s[t] += tmp;
        __syncthreads();
    }
    g_bsum[t] = s[t] - v;
}

__global__ void scanC_kernel(int N, int E) {
    int i = blockIdx.x * blockDim.x + threadIdx.x;
    if (i <= N) {
        int o = (i == N) ? E : (g_scan[i] + g_bsum[i / SCAN_BLK]);
        g_off[i] = o;
        if (i < N) g_cur[i] = o;
    }
}

__global__ void fill_kernel(const int* __restrict__ edge_dst, int E) {
    int i = blockIdx.x * blockDim.x + threadIdx.x;
    if (i < E) {
        int p = atomicAdd(&g_cur[edge_dst[i]], 1);
        g_eidx[p] = i;
    }
}

// ---------------------------------------------------------------------------
// Kernel 2a: W transpose + bf16 hi/lo split:  Bh[n][k]=bf16(w[k][n]), Bl=resid
// ---------------------------------------------------------------------------
__global__ void wsplit_kernel(const float* __restrict__ w,
                              __nv_bfloat16* __restrict__ bh,
                              __nv_bfloat16* __restrict__ bl) {
    int k = blockIdx.x;        // 0..255
    int n = threadIdx.x;       // 0..127
    float a = w[k * F_OUT + n];
    __nv_bfloat16 hi = __float2bfloat16_rn(a);
    float r = a - __bfloat162float(hi);
    bh[n * F_IN + k] = hi;
    bl[n * F_IN + k] = __float2bfloat16_rn(r);
}

// ---------------------------------------------------------------------------
// Kernel 2b: mma.sync bf16 GEMM (3xBF16):  h[M,128] = x[M,256] @ W
// CTA 128x128, 8 warps (4m x 2n), warp tile 32x64, m16n8k16, KC=32.
// SMEM u32 row stride 20 -> (g*20+t) mod 32 covers all banks, conflict-free.
// ---------------------------------------------------------------------------
#define KC       32
#define NCHUNK   (F_IN / KC)       // 8
#define ASU      20                // u32 per SMEM row (16 data + 4 pad)
#define SM_AH    0
#define SM_AL    (128 * ASU)
#define SM_BH    (2 * 128 * ASU)
#define SM_BL    (3 * 128 * ASU)
#define GEMM_SMEM_BYTES (4 * 128 * ASU * 4)   // 40960

__device__ __forceinline__ uint32_t pack_bf16(float a, float b) {
    __nv_bfloat162 t = __floats2bfloat162_rn(a, b);   // .x = a (low half)
    return *(uint32_t*)&t;
}

__device__ __forceinline__ void mma_bf16(float* d, const uint32_t* a,
                                         const uint32_t* b) {
    asm volatile(
        "mma.sync.aligned.m16n8k16.row.col.f32.bf16.bf16.f32 "
        "{%0, %1, %2, %3}, {%4, %5, %6, %7}, {%8, %9}, {%0, %1, %2, %3};"
        : "+f"(d[0]), "+f"(d[1]), "+f"(d[2]), "+f"(d[3])
        : "r"(a[0]), "r"(a[1]), "r"(a[2]), "r"(a[3]), "r"(b[0]), "r"(b[1]));
}

__global__ __launch_bounds__(256, 2)
void gemm_mma_kernel(const float* __restrict__ x,
                     const __nv_bfloat16* __restrict__ bh_g,
                     const __nv_bfloat16* __restrict__ bl_g,
                     float* __restrict__ h, int M) {
    extern __shared__ uint32_t smu[];
    const int tid  = threadIdx.x;
    const int wid  = tid >> 5;
    const int lane = tid & 31;
    const int g = lane >> 2;
    const int t = lane & 3;
    const int wm = wid & 3;
    const int wn = wid >> 2;
    const int block_row = blockIdx.x * 128;

    const uint32_t* bhu = (const uint32_t*)bh_g;   // [n][128] u32 rows
    const uint32_t* blu = (const uint32_t*)bl_g;

    float acc[2][8][4];
    #pragma unroll
    for (int i = 0; i < 2; i++)
        #pragma unroll
        for (int j = 0; j < 8; j++)
            #pragma unroll
            for (int q = 0; q < 4; q++) acc[i][j][q] = 0.0f;

    for (int c = 0; c < NCHUNK; c++) {
        if (c > 0) __syncthreads();
        // ---- A: 128 rows x 32 k; fp32 -> bf16 hi/lo, packed u32 pairs ----
        #pragma unroll
        for (int i = 0; i < 4; i++) {
            int fidx = i * 256 + tid;          // 1024 float4 slots
            int row = fidx >> 3, c4 = fidx & 7;
            int grow = block_row + row;
            float4 v = make_float4(0.f, 0.f, 0.f, 0.f);
            if (grow < M)
                v = *(const float4*)(x + (size_t)grow * F_IN + c * KC + c4 * 4);
            float h0 = __bfloat162float(__float2bfloat16_rn(v.x));
            float h1 = __bfloat162float(__float2bfloat16_rn(v.y));
            float h2 = __bfloat162float(__float2bfloat16_rn(v.z));
            float h3 = __bfloat162float(__float2bfloat16_rn(v.w));
            uint32_t base = row * ASU + c4 * 2;
            *(uint2*)&smu[SM_AH + base] =
                make_uint2(pack_bf16(h0, h1), pack_bf16(h2, h3));
            *(uint2*)&smu[SM_AL + base] =
                make_uint2(pack_bf16(v.x - h0, v.y - h1),
                           pack_bf16(v.z - h2, v.w - h3));
        }
        // ---- B: 128 n-rows x 32 k (pre-split bf16 in gmem) ----
        #pragma unroll
        for (int i = 0; i < 2; i++) {
            int fidx = i * 256 + tid;          // 512 uint4 slots
            int row = fidx >> 2, q = fidx & 3;
            const size_t go = (size_t)row * (F_IN / 2) + c * (KC / 2) + q * 4;
            uint4 vh = *(const uint4*)(bhu + go);
            uint4 vl = *(const uint4*)(blu + go);
            uint32_t base = row * ASU + q * 4;
            *(uint4*)&smu[SM_BH + base] = vh;
            *(uint4*)&smu[SM_BL + base] = vl;
        }
        __syncthreads();

        #pragma unroll
        for (int kp = 0; kp < KC / 2; kp += 8) {   // two k16 steps
            uint32_t ah[2][4], al[2][4];
            #pragma unroll
            for (int mt = 0; mt < 2; mt++) {
                int r0 = (wm * 32 + mt * 16 + g) * ASU + kp + t;
                int r8 = (wm * 32 + mt * 16 + g + 8) * ASU + kp + t;
                ah[mt][0] = smu[SM_AH + r0];
                ah[mt][1] = smu[SM_AH + r8];
                ah[mt][2] = smu[SM_AH + r0 + 4];
                ah[mt][3] = smu[SM_AH + r8 + 4];
                al[mt][0] = smu[SM_AL + r0];
                al[mt][1] = smu[SM_AL + r8];
                al[mt][2] = smu[SM_AL + r0 + 4];
                al[mt][3] = smu[SM_AL + r8 + 4];
            }
            #pragma unroll
            for (int nt = 0; nt < 8; nt++) {
                int nrow = (wn * 64 + nt * 8 + g) * ASU + kp + t;
                uint32_t bh[2], bl[2];
                bh[0] = smu[SM_BH + nrow];
                bh[1] = smu[SM_BH + nrow + 4];
                bl[0] = smu[SM_BL + nrow];
                bl[1] = smu[SM_BL + nrow + 4];
                #pragma unroll
                for (int mt = 0; mt < 2; mt++) {
                    mma_bf16(acc[mt][nt], ah[mt], bh);
                    mma_bf16(acc[mt][nt], al[mt], bh);
                    mma_bf16(acc[mt][nt], ah[mt], bl);
                }
            }
        }
    }

    // ---- writeback (same D layout as tf32 m16n8k8) ----
    #pragma unroll
    for (int mt = 0; mt < 2; mt++) {
        int row0 = block_row + wm * 32 + mt * 16 + g;
        int row8 = row0 + 8;
        #pragma unroll
        for (int nt = 0; nt < 8; nt++) {
            int col = wn * 64 + nt * 8 + 2 * t;
            if (row0 < M)
                *(float2*)(h + (size_t)row0 * F_OUT + col) =
                    make_float2(acc[mt][nt][0], acc[mt][nt][1]);
            if (row8 < M)
                *(float2*)(h + (size_t)row8 * F_OUT + col) =
                    make_float2(acc[mt][nt][2], acc[mt][nt][3]);
        }
    }
}

// ---------------------------------------------------------------------------
// Kernel 3: CSR aggregation — warp per dst node (unchanged + unroll hint).
// ---------------------------------------------------------------------------
__global__ __launch_bounds__(256)
void aggregate_kernel(const int* __restrict__ esrc,
                      const float* __restrict__ eval,
                      const float* __restrict__ h,
                      const float* __restrict__ bias,
                      float* __restrict__ out, int N) {
    const int warp = (blockIdx.x * blockDim.x + threadIdx.x) >> 5;
    const int lane = threadIdx.x & 31;
    if (warp >= N) return;

    const int s0 = g_off[warp];
    const int s1 = g_off[warp + 1];
    float4 acc = ((const float4*)bias)[lane];

    for (int base = s0; base < s1; base += 32) {
        int s = 0; float v = 0.0f;
        if (base + lane < s1) {
            int e = g_eidx[base + lane];
            s = esrc[e];
            v = eval[e];
        }
        const int cnt = min(32, s1 - base);
        #pragma unroll 4
        for (int j = 0; j < cnt; j++) {
            int   ss = __shfl_sync(0xFFFFFFFFu, s, j);
            float vv = __shfl_sync(0xFFFFFFFFu, v, j);
            float4 m = ((const float4*)(h + (size_t)ss * F_OUT))[lane];
            acc.x += m.x * vv; acc.y += m.y * vv;
            acc.z += m.z * vv; acc.w += m.w * vv;
        }
    }
    ((float4*)(out + (size_t)warp * F_OUT))[lane] = acc;
}

// ---------------------------------------------------------------------------
// Launch.  Inputs: x[f32], edge_src[i32], edge_dst[i32], edge_vals[f32],
//                  kernel[f32], bias[f32]
// ---------------------------------------------------------------------------
extern "C" void kernel_launch(void* const* d_in, const int* in_sizes, int n_in,
                              void* d_out, int out_size) {
    const float* x    = (const float*)d_in[0];
    const int*   esrc = (const int*)d_in[1];
    const int*   edst = (const int*)d_in[2];
    const float* eval = (const float*)d_in[3];
    const float* w    = (const float*)d_in[4];
    const float* bias = (const float*)d_in[5];
    float*       out  = (float*)d_out;

    const int M = in_sizes[0] / F_IN;     // 100000 nodes
    const int E = in_sizes[1];            // 1.6M edges
    const int n_pad  = ((M + SCAN_BLK - 1) / SCAN_BLK) * SCAN_BLK;
    const int n_sblk = n_pad / SCAN_BLK;  // 98

    float* h;
    __nv_bfloat16 *bh, *bl;
    cudaGetSymbolAddress((void**)&h,  g_h);
    cudaGetSymbolAddress((void**)&bh, g_Bh16);
    cudaGetSymbolAddress((void**)&bl, g_Bl16);

    // --- CSR build ---
    zero_cnt_kernel<<<(n_pad + 255) / 256, 256>>>(n_pad);
    count_kernel<<<(E + 255) / 256, 256>>>(edst, E);
    scanA_kernel<<<n_sblk, SCAN_BLK>>>();
    scanB_kernel<<<1, 256>>>(n_sblk);
    scanC_kernel<<<(M + 256) / 256, 256>>>(M, E);
    fill_kernel<<<(E + 255) / 256, 256>>>(edst, E);

    // --- h = x @ W (3xBF16 mma.sync) ---
    wsplit_kernel<<<F_IN, F_OUT>>>(w, bh, bl);
    {
        static int smem_set = 0;
        if (!smem_set) {
            cudaFuncSetAttribute(gemm_mma_kernel,
                                 cudaFuncAttributeMaxDynamicSharedMemorySize,
                                 GEMM_SMEM_BYTES);
            smem_set = 1;
        }
        int blocks = (M + 127) / 128;
        gemm_mma_kernel<<<blocks, 256, GEMM_SMEM_BYTES>>>(x, bh, bl, h, M);
    }

    // --- out = segment_sum + bias (warp per node) ---
    {
        int blocks = (M * 32 + 255) / 256;   // 12500
        aggregate_kernel<<<blocks, 256>>>(esrc, eval, h, bias, out, M);
    }
}

// round 7
// speedup vs baseline: 1.8035x; 1.1146x over previous
#include <cuda_runtime.h>
#include <cuda_bf16.h>
#include <cstdint>

#define F_IN     256
#define F_OUT    128
#define MAX_N    100352            // 98 * 1024, covers 100000
#define MAX_E    1600000
#define SCAN_BLK 1024

// Static scratch — __device__ globals (no allocation allowed).
__device__ float g_h[(size_t)100000 * F_OUT];        // h = x @ W (51.2 MB)
__device__ __nv_bfloat16 g_Bh16[F_IN * F_OUT];       // W^T hi bf16, [n][k]
__device__ __nv_bfloat16 g_Bl16[F_IN * F_OUT];       // W^T lo bf16, [n][k]
__device__ int   g_cnt[MAX_N];
__device__ int   g_scan[MAX_N];
__device__ int   g_bsum[256];
__device__ int   g_off[MAX_N + 1];
__device__ int   g_cur[MAX_N];
__device__ int   g_eidx[MAX_E];

// ---------------------------------------------------------------------------
// CSR build: count -> scanA -> scanB -> scanC -> fill  (unchanged, passing)
// ---------------------------------------------------------------------------
__global__ void zero_cnt_kernel(int n_pad) {
    int i = blockIdx.x * blockDim.x + threadIdx.x;
    if (i < n_pad) g_cnt[i] = 0;
}

__global__ void count_kernel(const int* __restrict__ edge_dst, int E) {
    int i = blockIdx.x * blockDim.x + threadIdx.x;
    if (i < E) atomicAdd(&g_cnt[edge_dst[i]], 1);
}

__global__ __launch_bounds__(SCAN_BLK)
void scanA_kernel() {
    __shared__ int s[SCAN_BLK];
    int t = threadIdx.x;
    int i = blockIdx.x * SCAN_BLK + t;
    int v = g_cnt[i];
    s[t] = v;
    __syncthreads();
    #pragma unroll
    for (int off = 1; off < SCAN_BLK; off <<= 1) {
        int tmp = (t >= off) ? s[t - off] : 0;
        __syncthreads();
        s[t] += tmp;
        __syncthreads();
    }
    g_scan[i] = s[t] - v;
    if (t == SCAN_BLK - 1) g_bsum[blockIdx.x] = s[t];
}

__global__ __launch_bounds__(256)
void scanB_kernel(int nblk) {
    __shared__ int s[256];
    int t = threadIdx.x;
    int v = (t < nblk) ? g_bsum[t] : 0;
    s[t] = v;
    __syncthreads();
    #pragma unroll
    for (int off = 1; off < 256; off <<= 1) {
        int tmp = (t >= off) ? s[t - off] : 0;
        __syncthreads();
        s[t] += tmp;
        __syncthreads();
    }
    g_bsum[t] = s[t] - v;
}

__global__ void scanC_kernel(int N, int E) {
    int i = blockIdx.x * blockDim.x + threadIdx.x;
    if (i <= N) {
        int o = (i == N) ? E : (g_scan[i] + g_bsum[i / SCAN_BLK]);
        g_off[i] = o;
        if (i < N) g_cur[i] = o;
    }
}

__global__ void fill_kernel(const int* __restrict__ edge_dst, int E) {
    int i = blockIdx.x * blockDim.x + threadIdx.x;
    if (i < E) {
        int p = atomicAdd(&g_cur[edge_dst[i]], 1);
        g_eidx[p] = i;
    }
}

// ---------------------------------------------------------------------------
// Kernel 2a: W transpose + bf16 hi/lo split
// ---------------------------------------------------------------------------
__global__ void wsplit_kernel(const float* __restrict__ w,
                              __nv_bfloat16* __restrict__ bh,
                              __nv_bfloat16* __restrict__ bl) {
    int k = blockIdx.x;        // 0..255
    int n = threadIdx.x;       // 0..127
    float a = w[k * F_OUT + n];
    __nv_bfloat16 hi = __float2bfloat16_rn(a);
    float r = a - __bfloat162float(hi);
    bh[n * F_IN + k] = hi;
    bl[n * F_IN + k] = __float2bfloat16_rn(r);
}

// ---------------------------------------------------------------------------
// Kernel 2b: mma.sync bf16 GEMM (3xBF16) — unchanged from passing R6.
// ---------------------------------------------------------------------------
#define KC       32
#define NCHUNK   (F_IN / KC)       // 8
#define ASU      20                // u32 per SMEM row (16 data + 4 pad)
#define SM_AH    0
#define SM_AL    (128 * ASU)
#define SM_BH    (2 * 128 * ASU)
#define SM_BL    (3 * 128 * ASU)
#define GEMM_SMEM_BYTES (4 * 128 * ASU * 4)   // 40960

__device__ __forceinline__ uint32_t pack_bf16(float a, float b) {
    __nv_bfloat162 t = __floats2bfloat162_rn(a, b);   // .x = a (low half)
    return *(uint32_t*)&t;
}

__device__ __forceinline__ void mma_bf16(float* d, const uint32_t* a,
                                         const uint32_t* b) {
    asm volatile(
        "mma.sync.aligned.m16n8k16.row.col.f32.bf16.bf16.f32 "
        "{%0, %1, %2, %3}, {%4, %5, %6, %7}, {%8, %9}, {%0, %1, %2, %3};"
        : "+f"(d[0]), "+f"(d[1]), "+f"(d[2]), "+f"(d[3])
        : "r"(a[0]), "r"(a[1]), "r"(a[2]), "r"(a[3]), "r"(b[0]), "r"(b[1]));
}

__global__ __launch_bounds__(256, 2)
void gemm_mma_kernel(const float* __restrict__ x,
                     const __nv_bfloat16* __restrict__ bh_g,
                     const __nv_bfloat16* __restrict__ bl_g,
                     float* __restrict__ h, int M) {
    extern __shared__ uint32_t smu[];
    const int tid  = threadIdx.x;
    const int wid  = tid >> 5;
    const int lane = tid & 31;
    const int g = lane >> 2;
    const int t = lane & 3;
    const int wm = wid & 3;
    const int wn = wid >> 2;
    const int block_row = blockIdx.x * 128;

    const uint32_t* bhu = (const uint32_t*)bh_g;   // [n][128] u32 rows
    const uint32_t* blu = (const uint32_t*)bl_g;

    float acc[2][8][4];
    #pragma unroll
    for (int i = 0; i < 2; i++)
        #pragma unroll
        for (int j = 0; j < 8; j++)
            #pragma unroll
            for (int q = 0; q < 4; q++) acc[i][j][q] = 0.0f;

    for (int c = 0; c < NCHUNK; c++) {
        if (c > 0) __syncthreads();
        // ---- A: 128 rows x 32 k; fp32 -> bf16 hi/lo, packed u32 pairs ----
        #pragma unroll
        for (int i = 0; i < 4; i++) {
            int fidx = i * 256 + tid;          // 1024 float4 slots
            int row = fidx >> 3, c4 = fidx & 7;
            int grow = block_row + row;
            float4 v = make_float4(0.f, 0.f, 0.f, 0.f);
            if (grow < M)
                v = *(const float4*)(x + (size_t)grow * F_IN + c * KC + c4 * 4);
            float h0 = __bfloat162float(__float2bfloat16_rn(v.x));
            float h1 = __bfloat162float(__float2bfloat16_rn(v.y));
            float h2 = __bfloat162float(__float2bfloat16_rn(v.z));
            float h3 = __bfloat162float(__float2bfloat16_rn(v.w));
            uint32_t base = row * ASU + c4 * 2;
            *(uint2*)&smu[SM_AH + base] =
                make_uint2(pack_bf16(h0, h1), pack_bf16(h2, h3));
            *(uint2*)&smu[SM_AL + base] =
                make_uint2(pack_bf16(v.x - h0, v.y - h1),
                           pack_bf16(v.z - h2, v.w - h3));
        }
        // ---- B: 128 n-rows x 32 k (pre-split bf16 in gmem) ----
        #pragma unroll
        for (int i = 0; i < 2; i++) {
            int fidx = i * 256 + tid;          // 512 uint4 slots
            int row = fidx >> 2, q = fidx & 3;
            const size_t go = (size_t)row * (F_IN / 2) + c * (KC / 2) + q * 4;
            uint4 vh = *(const uint4*)(bhu + go);
            uint4 vl = *(const uint4*)(blu + go);
            uint32_t base = row * ASU + q * 4;
            *(uint4*)&smu[SM_BH + base] = vh;
            *(uint4*)&smu[SM_BL + base] = vl;
        }
        __syncthreads();

        #pragma unroll
        for (int kp = 0; kp < KC / 2; kp += 8) {   // two k16 steps
            uint32_t ah[2][4], al[2][4];
            #pragma unroll
            for (int mt = 0; mt < 2; mt++) {
                int r0 = (wm * 32 + mt * 16 + g) * ASU + kp + t;
                int r8 = (wm * 32 + mt * 16 + g + 8) * ASU + kp + t;
                ah[mt][0] = smu[SM_AH + r0];
                ah[mt][1] = smu[SM_AH + r8];
                ah[mt][2] = smu[SM_AH + r0 + 4];
                ah[mt][3] = smu[SM_AH + r8 + 4];
                al[mt][0] = smu[SM_AL + r0];
                al[mt][1] = smu[SM_AL + r8];
                al[mt][2] = smu[SM_AL + r0 + 4];
                al[mt][3] = smu[SM_AL + r8 + 4];
            }
            #pragma unroll
            for (int nt = 0; nt < 8; nt++) {
                int nrow = (wn * 64 + nt * 8 + g) * ASU + kp + t;
                uint32_t bh[2], bl[2];
                bh[0] = smu[SM_BH + nrow];
                bh[1] = smu[SM_BH + nrow + 4];
                bl[0] = smu[SM_BL + nrow];
                bl[1] = smu[SM_BL + nrow + 4];
                #pragma unroll
                for (int mt = 0; mt < 2; mt++) {
                    mma_bf16(acc[mt][nt], ah[mt], bh);
                    mma_bf16(acc[mt][nt], al[mt], bh);
                    mma_bf16(acc[mt][nt], ah[mt], bl);
                }
            }
        }
    }

    #pragma unroll
    for (int mt = 0; mt < 2; mt++) {
        int row0 = block_row + wm * 32 + mt * 16 + g;
        int row8 = row0 + 8;
        #pragma unroll
        for (int nt = 0; nt < 8; nt++) {
            int col = wn * 64 + nt * 8 + 2 * t;
            if (row0 < M)
                *(float2*)(h + (size_t)row0 * F_OUT + col) =
                    make_float2(acc[mt][nt][0], acc[mt][nt][1]);
            if (row8 < M)
                *(float2*)(h + (size_t)row8 * F_OUT + col) =
                    make_float2(acc[mt][nt][2], acc[mt][nt][3]);
        }
    }
}

// ---------------------------------------------------------------------------
// Kernel 3: CSR aggregation — warp per dst node (unchanged, passing).
// ---------------------------------------------------------------------------
__global__ __launch_bounds__(256)
void aggregate_kernel(const int* __restrict__ esrc,
                      const float* __restrict__ eval,
                      const float* __restrict__ h,
                      const float* __restrict__ bias,
                      float* __restrict__ out, int N) {
    const int warp = (blockIdx.x * blockDim.x + threadIdx.x) >> 5;
    const int lane = threadIdx.x & 31;
    if (warp >= N) return;

    const int s0 = g_off[warp];
    const int s1 = g_off[warp + 1];
    float4 acc = ((const float4*)bias)[lane];

    for (int base = s0; base < s1; base += 32) {
        int s = 0; float v = 0.0f;
        if (base + lane < s1) {
            int e = g_eidx[base + lane];
            s = esrc[e];
            v = eval[e];
        }
        const int cnt = min(32, s1 - base);
        #pragma unroll 4
        for (int j = 0; j < cnt; j++) {
            int   ss = __shfl_sync(0xFFFFFFFFu, s, j);
            float vv = __shfl_sync(0xFFFFFFFFu, v, j);
            float4 m = ((const float4*)(h + (size_t)ss * F_OUT))[lane];
            acc.x += m.x * vv; acc.y += m.y * vv;
            acc.z += m.z * vv; acc.w += m.w * vv;
        }
    }
    ((float4*)(out + (size_t)warp * F_OUT))[lane] = acc;
}

// ---------------------------------------------------------------------------
// Launch.  Inputs: x[f32], edge_src[i32], edge_dst[i32], edge_vals[f32],
//                  kernel[f32], bias[f32]
// CSR build runs on a forked side stream, overlapped with wsplit+GEMM;
// both join before aggregate. Standard stream-capture fork/join pattern.
// ---------------------------------------------------------------------------
extern "C" void kernel_launch(void* const* d_in, const int* in_sizes, int n_in,
                              void* d_out, int out_size) {
    const float* x    = (const float*)d_in[0];
    const int*   esrc = (const int*)d_in[1];
    const int*   edst = (const int*)d_in[2];
    const float* eval = (const float*)d_in[3];
    const float* w    = (const float*)d_in[4];
    const float* bias = (const float*)d_in[5];
    float*       out  = (float*)d_out;

    const int M = in_sizes[0] / F_IN;     // 100000 nodes
    const int E = in_sizes[1];            // 1.6M edges
    const int n_pad  = ((M + SCAN_BLK - 1) / SCAN_BLK) * SCAN_BLK;
    const int n_sblk = n_pad / SCAN_BLK;  // 98

    float* h;
    __nv_bfloat16 *bh, *bl;
    cudaGetSymbolAddress((void**)&h,  g_h);
    cudaGetSymbolAddress((void**)&bh, g_Bh16);
    cudaGetSymbolAddress((void**)&bl, g_Bl16);

    static cudaStream_t s2 = nullptr;
    static cudaEvent_t ev_fork = nullptr, ev_join = nullptr;
    static int init_done = 0;
    if (!init_done) {
        cudaStreamCreateWithFlags(&s2, cudaStreamNonBlocking);
        cudaEventCreateWithFlags(&ev_fork, cudaEventDisableTiming);
        cudaEventCreateWithFlags(&ev_join, cudaEventDisableTiming);
        cudaFuncSetAttribute(gemm_mma_kernel,
                             cudaFuncAttributeMaxDynamicSharedMemorySize,
                             GEMM_SMEM_BYTES);
        init_done = 1;
    }

    // ---- fork: CSR build on s2 ----
    cudaEventRecord(ev_fork, 0);
    cudaStreamWaitEvent(s2, ev_fork, 0);
    zero_cnt_kernel<<<(n_pad + 255) / 256, 256, 0, s2>>>(n_pad);
    count_kernel<<<(E + 255) / 256, 256, 0, s2>>>(edst, E);
    scanA_kernel<<<n_sblk, SCAN_BLK, 0, s2>>>();
    scanB_kernel<<<1, 256, 0, s2>>>(n_sblk);
    scanC_kernel<<<(M + 256) / 256, 256, 0, s2>>>(M, E);
    fill_kernel<<<(E + 255) / 256, 256, 0, s2>>>(edst, E);
    cudaEventRecord(ev_join, s2);

    // ---- main stream: dense path ----
    wsplit_kernel<<<F_IN, F_OUT>>>(w, bh, bl);
    {
        int blocks = (M + 127) / 128;
        gemm_mma_kernel<<<blocks, 256, GEMM_SMEM_BYTES>>>(x, bh, bl, h, M);
    }

    // ---- join, then aggregate ----
    cudaStreamWaitEvent(0, ev_join, 0);
    {
        int blocks = (M * 32 + 255) / 256;   // 12500
        aggregate_kernel<<<blocks, 256>>>(esrc, eval, h, bias, out, M);
    }
}

// round 8
// speedup vs baseline: 2.1504x; 1.1924x over previous
#include <cuda_runtime.h>
#include <cuda_fp16.h>
#include <cstdint>

#define F_IN     256
#define F_OUT    128
#define MAX_N    100352            // 98 * 1024, covers 100000
#define MAX_E    1600000
#define SCAN_BLK 1024

// Static scratch — __device__ globals (no allocation allowed).
__device__ float g_h[(size_t)100000 * F_OUT];   // h = x @ W (51.2 MB)
__device__ __half g_Bh16[F_IN * F_OUT];         // W^T hi fp16, [n][k]
__device__ __half g_Bl16[F_IN * F_OUT];         // W^T lo fp16, [n][k]
__device__ int   g_cnt[MAX_N];
__device__ int   g_scan[MAX_N];
__device__ int   g_bsum[256];
__device__ int   g_off[MAX_N + 1];
__device__ int   g_cur[MAX_N];
__device__ int2  g_edge[MAX_E];                 // (src, val_bits) in CSR order

// ---------------------------------------------------------------------------
// CSR build: count -> scanA -> scanB -> scanC -> fill(packed)
// ---------------------------------------------------------------------------
__global__ void zero_cnt_kernel(int n_pad) {
    int i = blockIdx.x * blockDim.x + threadIdx.x;
    if (i < n_pad) g_cnt[i] = 0;
}

__global__ void count_kernel(const int* __restrict__ edge_dst, int E) {
    int i = blockIdx.x * blockDim.x + threadIdx.x;
    if (i < E) atomicAdd(&g_cnt[edge_dst[i]], 1);
}

__global__ __launch_bounds__(SCAN_BLK)
void scanA_kernel() {
    __shared__ int s[SCAN_BLK];
    int t = threadIdx.x;
    int i = blockIdx.x * SCAN_BLK + t;
    int v = g_cnt[i];
    s[t] = v;
    __syncthreads();
    #pragma unroll
    for (int off = 1; off < SCAN_BLK; off <<= 1) {
        int tmp = (t >= off) ? s[t - off] : 0;
        __syncthreads();
        s[t] += tmp;
        __syncthreads();
    }
    g_scan[i] = s[t] - v;
    if (t == SCAN_BLK - 1) g_bsum[blockIdx.x] = s[t];
}

__global__ __launch_bounds__(256)
void scanB_kernel(int nblk) {
    __shared__ int s[256];
    int t = threadIdx.x;
    int v = (t < nblk) ? g_bsum[t] : 0;
    s[t] = v;
    __syncthreads();
    #pragma unroll
    for (int off = 1; off < 256; off <<= 1) {
        int tmp = (t >= off) ? s[t - off] : 0;
        __syncthreads();
        s[t] += tmp;
        __syncthreads();
    }
    g_bsum[t] = s[t] - v;
}

__global__ void scanC_kernel(int N, int E) {
    int i = blockIdx.x * blockDim.x + threadIdx.x;
    if (i <= N) {
        int o = (i == N) ? E : (g_scan[i] + g_bsum[i / SCAN_BLK]);
        g_off[i] = o;
        if (i < N) g_cur[i] = o;
    }
}

__global__ void fill_kernel(const int* __restrict__ edge_dst,
                            const int* __restrict__ edge_src,
                            const float* __restrict__ edge_vals, int E) {
    int i = blockIdx.x * blockDim.x + threadIdx.x;
    if (i < E) {
        int p = atomicAdd(&g_cur[edge_dst[i]], 1);
        g_edge[p] = make_int2(edge_src[i], __float_as_int(edge_vals[i]));
    }
}

// ---------------------------------------------------------------------------
// Kernel 2a: W transpose + fp16 hi/lo split:  Bh[n][k]=fp16(w[k][n]), Bl=resid
// ---------------------------------------------------------------------------
__global__ void wsplit_kernel(const float* __restrict__ w,
                              __half* __restrict__ bh,
                              __half* __restrict__ bl) {
    int k = blockIdx.x;        // 0..255
    int n = threadIdx.x;       // 0..127
    float a = w[k * F_OUT + n];
    __half hi = __float2half_rn(a);
    float r = a - __half2float(hi);
    bh[n * F_IN + k] = hi;
    bl[n * F_IN + k] = __float2half_rn(r);
}

// ---------------------------------------------------------------------------
// Kernel 2b: mma.sync fp16 GEMM (2-pass):  h = x @ W,  D = A*Bh + A*Bl
// A = fp16(x) single rounding (dropped residual ~2^-11 rel).
// CTA 128x128, 8 warps (4m x 2n), warp tile 32x64, m16n8k16, KC=32.
// SMEM u32 row stride 20 -> conflict-free fragment loads.
// ---------------------------------------------------------------------------
#define KC       32
#define NCHUNK   (F_IN / KC)       // 8
#define ASU      20                // u32 per SMEM row (16 data + 4 pad)
#define SM_A     0
#define SM_BH    (128 * ASU)
#define SM_BL    (2 * 128 * ASU)
#define GEMM_SMEM_BYTES (3 * 128 * ASU * 4)   // 30720

__device__ __forceinline__ uint32_t pack_h2(float a, float b) {
    __half2 t = __floats2half2_rn(a, b);   // .x = a (low half)
    return *(uint32_t*)&t;
}

__device__ __forceinline__ void mma_f16(float* d, const uint32_t* a,
                                        const uint32_t* b) {
    asm volatile(
        "mma.sync.aligned.m16n8k16.row.col.f32.f16.f16.f32 "
        "{%0, %1, %2, %3}, {%4, %5, %6, %7}, {%8, %9}, {%0, %1, %2, %3};"
        : "+f"(d[0]), "+f"(d[1]), "+f"(d[2]), "+f"(d[3])
        : "r"(a[0]), "r"(a[1]), "r"(a[2]), "r"(a[3]), "r"(b[0]), "r"(b[1]));
}

__global__ __launch_bounds__(256, 2)
void gemm_mma_kernel(const float* __restrict__ x,
                     const __half* __restrict__ bh_g,
                     const __half* __restrict__ bl_g,
                     float* __restrict__ h, int M) {
    extern __shared__ uint32_t smu[];
    const int tid  = threadIdx.x;
    const int wid  = tid >> 5;
    const int lane = tid & 31;
    const int g = lane >> 2;
    const int t = lane & 3;
    const int wm = wid & 3;
    const int wn = wid >> 2;
    const int block_row = blockIdx.x * 128;

    const uint32_t* bhu = (const uint32_t*)bh_g;   // [n][128] u32 rows
    const uint32_t* blu = (const uint32_t*)bl_g;

    float acc[2][8][4];
    #pragma unroll
    for (int i = 0; i < 2; i++)
        #pragma unroll
        for (int j = 0; j < 8; j++)
            #pragma unroll
            for (int q = 0; q < 4; q++) acc[i][j][q] = 0.0f;

    for (int c = 0; c < NCHUNK; c++) {
        if (c > 0) __syncthreads();
        // ---- A: 128 rows x 32 k; fp32 -> fp16, packed u32 pairs ----
        #pragma unroll
        for (int i = 0; i < 4; i++) {
            int fidx = i * 256 + tid;          // 1024 float4 slots
            int row = fidx >> 3, c4 = fidx & 7;
            int grow = block_row + row;
            float4 v = make_float4(0.f, 0.f, 0.f, 0.f);
            if (grow < M)
                v = *(const float4*)(x + (size_t)grow * F_IN + c * KC + c4 * 4);
            uint32_t base = row * ASU + c4 * 2;
            *(uint2*)&smu[SM_A + base] =
                make_uint2(pack_h2(v.x, v.y), pack_h2(v.z, v.w));
        }
        // ---- B: 128 n-rows x 32 k (pre-split fp16 hi/lo in gmem) ----
        #pragma unroll
        for (int i = 0; i < 2; i++) {
            int fidx = i * 256 + tid;          // 512 uint4 slots
            int row = fidx >> 2, q = fidx & 3;
            const size_t go = (size_t)row * (F_IN / 2) + c * (KC / 2) + q * 4;
            uint4 vh = *(const uint4*)(bhu + go);
            uint4 vl = *(const uint4*)(blu + go);
            uint32_t base = row * ASU + q * 4;
            *(uint4*)&smu[SM_BH + base] = vh;
            *(uint4*)&smu[SM_BL + base] = vl;
        }
        __syncthreads();

        #pragma unroll
        for (int kp = 0; kp < KC / 2; kp += 8) {   // two k16 steps
            uint32_t a[2][4];
            #pragma unroll
            for (int mt = 0; mt < 2; mt++) {
                int r0 = (wm * 32 + mt * 16 + g) * ASU + kp + t;
                int r8 = (wm * 32 + mt * 16 + g + 8) * ASU + kp + t;
                a[mt][0] = smu[SM_A + r0];
                a[mt][1] = smu[SM_A + r8];
                a[mt][2] = smu[SM_A + r0 + 4];
                a[mt][3] = smu[SM_A + r8 + 4];
            }
            #pragma unroll
            for (int nt = 0; nt < 8; nt++) {
                int nrow = (wn * 64 + nt * 8 + g) * ASU + kp + t;
                uint32_t bh[2], bl[2];
                bh[0] = smu[SM_BH + nrow];
                bh[1] = smu[SM_BH + nrow + 4];
                bl[0] = smu[SM_BL + nrow];
                bl[1] = smu[SM_BL + nrow + 4];
                #pragma unroll
                for (int mt = 0; mt < 2; mt++) {
                    mma_f16(acc[mt][nt], a[mt], bh);
                    mma_f16(acc[mt][nt], a[mt], bl);
                }
            }
        }
    }

    #pragma unroll
    for (int mt = 0; mt < 2; mt++) {
        int row0 = block_row + wm * 32 + mt * 16 + g;
        int row8 = row0 + 8;
        #pragma unroll
        for (int nt = 0; nt < 8; nt++) {
            int col = wn * 64 + nt * 8 + 2 * t;
            if (row0 < M)
                *(float2*)(h + (size_t)row0 * F_OUT + col) =
                    make_float2(acc[mt][nt][0], acc[mt][nt][1]);
            if (row8 < M)
                *(float2*)(h + (size_t)row8 * F_OUT + col) =
                    make_float2(acc[mt][nt][2], acc[mt][nt][3]);
        }
    }
}

// ---------------------------------------------------------------------------
// Kernel 3: CSR aggregation — warp per dst node, sequential packed edges.
// ---------------------------------------------------------------------------
__global__ __launch_bounds__(256)
void aggregate_kernel(const float* __restrict__ h,
                      const float* __restrict__ bias,
                      float* __restrict__ out, int N) {
    const int warp = (blockIdx.x * blockDim.x + threadIdx.x) >> 5;
    const int lane = threadIdx.x & 31;
    if (warp >= N) return;

    const int s0 = g_off[warp];
    const int s1 = g_off[warp + 1];
    float4 acc = ((const float4*)bias)[lane];

    for (int base = s0; base < s1; base += 32) {
        int s = 0; float v = 0.0f;
        if (base + lane < s1) {
            int2 e = g_edge[base + lane];
            s = e.x;
            v = __int_as_float(e.y);
        }
        const int cnt = min(32, s1 - base);
        #pragma unroll 4
        for (int j = 0; j < cnt; j++) {
            int   ss = __shfl_sync(0xFFFFFFFFu, s, j);
            float vv = __shfl_sync(0xFFFFFFFFu, v, j);
            float4 m = ((const float4*)(h + (size_t)ss * F_OUT))[lane];
            acc.x += m.x * vv; acc.y += m.y * vv;
            acc.z += m.z * vv; acc.w += m.w * vv;
        }
    }
    ((float4*)(out + (size_t)warp * F_OUT))[lane] = acc;
}

// ---------------------------------------------------------------------------
// Launch.  Inputs: x[f32], edge_src[i32], edge_dst[i32], edge_vals[f32],
//                  kernel[f32], bias[f32]
// CSR build forked onto a side stream, overlapped with wsplit+GEMM.
// ---------------------------------------------------------------------------
extern "C" void kernel_launch(void* const* d_in, const int* in_sizes, int n_in,
                              void* d_out, int out_size) {
    const float* x    = (const float*)d_in[0];
    const int*   esrc = (const int*)d_in[1];
    const int*   edst = (const int*)d_in[2];
    const float* eval = (const float*)d_in[3];
    const float* w    = (const float*)d_in[4];
    const float* bias = (const float*)d_in[5];
    float*       out  = (float*)d_out;

    const int M = in_sizes[0] / F_IN;     // 100000 nodes
    const int E = in_sizes[1];            // 1.6M edges
    const int n_pad  = ((M + SCAN_BLK - 1) / SCAN_BLK) * SCAN_BLK;
    const int n_sblk = n_pad / SCAN_BLK;  // 98

    float* h;
    __half *bh, *bl;
    cudaGetSymbolAddress((void**)&h,  g_h);
    cudaGetSymbolAddress((void**)&bh, g_Bh16);
    cudaGetSymbolAddress((void**)&bl, g_Bl16);

    static cudaStream_t s2 = nullptr;
    static cudaEvent_t ev_fork = nullptr, ev_join = nullptr;
    static int init_done = 0;
    if (!init_done) {
        cudaStreamCreateWithFlags(&s2, cudaStreamNonBlocking);
        cudaEventCreateWithFlags(&ev_fork, cudaEventDisableTiming);
        cudaEventCreateWithFlags(&ev_join, cudaEventDisableTiming);
        cudaFuncSetAttribute(gemm_mma_kernel,
                             cudaFuncAttributeMaxDynamicSharedMemorySize,
                             GEMM_SMEM_BYTES);
        init_done = 1;
    }

    // ---- fork: CSR build on s2 ----
    cudaEventRecord(ev_fork, 0);
    cudaStreamWaitEvent(s2, ev_fork, 0);
    zero_cnt_kernel<<<(n_pad + 255) / 256, 256, 0, s2>>>(n_pad);
    count_kernel<<<(E + 255) / 256, 256, 0, s2>>>(edst, E);
    scanA_kernel<<<n_sblk, SCAN_BLK, 0, s2>>>();
    scanB_kernel<<<1, 256, 0, s2>>>(n_sblk);
    scanC_kernel<<<(M + 256) / 256, 256, 0, s2>>>(M, E);
    fill_kernel<<<(E + 255) / 256, 256, 0, s2>>>(edst, esrc, eval, E);
    cudaEventRecord(ev_join, s2);

    // ---- main stream: dense path ----
    wsplit_kernel<<<F_IN, F_OUT>>>(w, bh, bl);
    {
        int blocks = (M + 127) / 128;
        gemm_mma_kernel<<<blocks, 256, GEMM_SMEM_BYTES>>>(x, bh, bl, h, M);
    }

    // ---- join, then aggregate ----
    cudaStreamWaitEvent(0, ev_join, 0);
    {
        int blocks = (M * 32 + 255) / 256;   // 12500
        aggregate_kernel<<<blocks, 256>>>(h, bias, out, M);
    }
}

// round 9
// speedup vs baseline: 2.4274x; 1.1288x over previous
#include <cuda_runtime.h>
#include <cuda_fp16.h>
#include <cstdint>

#define F_IN     256
#define F_OUT    128
#define MAX_N    100352            // 98 * 1024, covers 100000
#define MAX_E    1600000
#define SCAN_BLK 1024

// Static scratch — __device__ globals (no allocation allowed).
__device__ __half g_h16[(size_t)100000 * F_OUT];  // h = x @ W, fp16 (25.6 MB)
__device__ __half g_Bh16[F_IN * F_OUT];           // W^T hi fp16, [n][k]
__device__ __half g_Bl16[F_IN * F_OUT];           // W^T lo fp16, [n][k]
__device__ int   g_cnt[MAX_N];
__device__ int   g_scan[MAX_N];
__device__ int   g_bsum[256];
__device__ int   g_off[MAX_N + 1];
__device__ int   g_cur[MAX_N];
__device__ int2  g_edge[MAX_E];                   // (src, val_bits) CSR order

// ---------------------------------------------------------------------------
// CSR build: count -> scanA -> scanB -> scanC -> fill(packed)  (unchanged)
// ---------------------------------------------------------------------------
__global__ void zero_cnt_kernel(int n_pad) {
    int i = blockIdx.x * blockDim.x + threadIdx.x;
    if (i < n_pad) g_cnt[i] = 0;
}

__global__ void count_kernel(const int* __restrict__ edge_dst, int E) {
    int i = blockIdx.x * blockDim.x + threadIdx.x;
    if (i < E) atomicAdd(&g_cnt[edge_dst[i]], 1);
}

__global__ __launch_bounds__(SCAN_BLK)
void scanA_kernel() {
    __shared__ int s[SCAN_BLK];
    int t = threadIdx.x;
    int i = blockIdx.x * SCAN_BLK + t;
    int v = g_cnt[i];
    s[t] = v;
    __syncthreads();
    #pragma unroll
    for (int off = 1; off < SCAN_BLK; off <<= 1) {
        int tmp = (t >= off) ? s[t - off] : 0;
        __syncthreads();
        s[t] += tmp;
        __syncthreads();
    }
    g_scan[i] = s[t] - v;
    if (t == SCAN_BLK - 1) g_bsum[blockIdx.x] = s[t];
}

__global__ __launch_bounds__(256)
void scanB_kernel(int nblk) {
    __shared__ int s[256];
    int t = threadIdx.x;
    int v = (t < nblk) ? g_bsum[t] : 0;
    s[t] = v;
    __syncthreads();
    #pragma unroll
    for (int off = 1; off < 256; off <<= 1) {
        int tmp = (t >= off) ? s[t - off] : 0;
        __syncthreads();
        s[t] += tmp;
        __syncthreads();
    }
    g_bsum[t] = s[t] - v;
}

__global__ void scanC_kernel(int N, int E) {
    int i = blockIdx.x * blockDim.x + threadIdx.x;
    if (i <= N) {
        int o = (i == N) ? E : (g_scan[i] + g_bsum[i / SCAN_BLK]);
        g_off[i] = o;
        if (i < N) g_cur[i] = o;
    }
}

__global__ void fill_kernel(const int* __restrict__ edge_dst,
                            const int* __restrict__ edge_src,
                            const float* __restrict__ edge_vals, int E) {
    int i = blockIdx.x * blockDim.x + threadIdx.x;
    if (i < E) {
        int p = atomicAdd(&g_cur[edge_dst[i]], 1);
        g_edge[p] = make_int2(edge_src[i], __float_as_int(edge_vals[i]));
    }
}

// ---------------------------------------------------------------------------
// Kernel 2a: W transpose + fp16 hi/lo split
// ---------------------------------------------------------------------------
__global__ void wsplit_kernel(const float* __restrict__ w,
                              __half* __restrict__ bh,
                              __half* __restrict__ bl) {
    int k = blockIdx.x;        // 0..255
    int n = threadIdx.x;       // 0..127
    float a = w[k * F_OUT + n];
    __half hi = __float2half_rn(a);
    float r = a - __half2float(hi);
    bh[n * F_IN + k] = hi;
    bl[n * F_IN + k] = __float2half_rn(r);
}

// ---------------------------------------------------------------------------
// Kernel 2b: mma.sync fp16 GEMM (2-pass), h written as fp16.
// ---------------------------------------------------------------------------
#define KC       32
#define NCHUNK   (F_IN / KC)       // 8
#define ASU      20                // u32 per SMEM row (16 data + 4 pad)
#define SM_A     0
#define SM_BH    (128 * ASU)
#define SM_BL    (2 * 128 * ASU)
#define GEMM_SMEM_BYTES (3 * 128 * ASU * 4)   // 30720

__device__ __forceinline__ uint32_t pack_h2(float a, float b) {
    __half2 t = __floats2half2_rn(a, b);   // .x = a (low half)
    return *(uint32_t*)&t;
}

__device__ __forceinline__ void mma_f16(float* d, const uint32_t* a,
                                        const uint32_t* b) {
    asm volatile(
        "mma.sync.aligned.m16n8k16.row.col.f32.f16.f16.f32 "
        "{%0, %1, %2, %3}, {%4, %5, %6, %7}, {%8, %9}, {%0, %1, %2, %3};"
        : "+f"(d[0]), "+f"(d[1]), "+f"(d[2]), "+f"(d[3])
        : "r"(a[0]), "r"(a[1]), "r"(a[2]), "r"(a[3]), "r"(b[0]), "r"(b[1]));
}

__global__ __launch_bounds__(256, 2)
void gemm_mma_kernel(const float* __restrict__ x,
                     const __half* __restrict__ bh_g,
                     const __half* __restrict__ bl_g,
                     __half* __restrict__ h16, int M) {
    extern __shared__ uint32_t smu[];
    const int tid  = threadIdx.x;
    const int wid  = tid >> 5;
    const int lane = tid & 31;
    const int g = lane >> 2;
    const int t = lane & 3;
    const int wm = wid & 3;
    const int wn = wid >> 2;
    const int block_row = blockIdx.x * 128;

    const uint32_t* bhu = (const uint32_t*)bh_g;   // [n][128] u32 rows
    const uint32_t* blu = (const uint32_t*)bl_g;
    uint32_t* hu = (uint32_t*)h16;                 // h as u32 (half2) words

    float acc[2][8][4];
    #pragma unroll
    for (int i = 0; i < 2; i++)
        #pragma unroll
        for (int j = 0; j < 8; j++)
            #pragma unroll
            for (int q = 0; q < 4; q++) acc[i][j][q] = 0.0f;

    for (int c = 0; c < NCHUNK; c++) {
        if (c > 0) __syncthreads();
        // ---- A: 128 rows x 32 k; fp32 -> fp16, packed u32 pairs ----
        #pragma unroll
        for (int i = 0; i < 4; i++) {
            int fidx = i * 256 + tid;          // 1024 float4 slots
            int row = fidx >> 3, c4 = fidx & 7;
            int grow = block_row + row;
            float4 v = make_float4(0.f, 0.f, 0.f, 0.f);
            if (grow < M)
                v = *(const float4*)(x + (size_t)grow * F_IN + c * KC + c4 * 4);
            uint32_t base = row * ASU + c4 * 2;
            *(uint2*)&smu[SM_A + base] =
                make_uint2(pack_h2(v.x, v.y), pack_h2(v.z, v.w));
        }
        // ---- B: 128 n-rows x 32 k (pre-split fp16 hi/lo in gmem) ----
        #pragma unroll
        for (int i = 0; i < 2; i++) {
            int fidx = i * 256 + tid;          // 512 uint4 slots
            int row = fidx >> 2, q = fidx & 3;
            const size_t go = (size_t)row * (F_IN / 2) + c * (KC / 2) + q * 4;
            uint4 vh = *(const uint4*)(bhu + go);
            uint4 vl = *(const uint4*)(blu + go);
            uint32_t base = row * ASU + q * 4;
            *(uint4*)&smu[SM_BH + base] = vh;
            *(uint4*)&smu[SM_BL + base] = vl;
        }
        __syncthreads();

        #pragma unroll
        for (int kp = 0; kp < KC / 2; kp += 8) {   // two k16 steps
            uint32_t a[2][4];
            #pragma unroll
            for (int mt = 0; mt < 2; mt++) {
                int r0 = (wm * 32 + mt * 16 + g) * ASU + kp + t;
                int r8 = (wm * 32 + mt * 16 + g + 8) * ASU + kp + t;
                a[mt][0] = smu[SM_A + r0];
                a[mt][1] = smu[SM_A + r8];
                a[mt][2] = smu[SM_A + r0 + 4];
                a[mt][3] = smu[SM_A + r8 + 4];
            }
            #pragma unroll
            for (int nt = 0; nt < 8; nt++) {
                int nrow = (wn * 64 + nt * 8 + g) * ASU + kp + t;
                uint32_t bh[2], bl[2];
                bh[0] = smu[SM_BH + nrow];
                bh[1] = smu[SM_BH + nrow + 4];
                bl[0] = smu[SM_BL + nrow];
                bl[1] = smu[SM_BL + nrow + 4];
                #pragma unroll
                for (int mt = 0; mt < 2; mt++) {
                    mma_f16(acc[mt][nt], a[mt], bh);
                    mma_f16(acc[mt][nt], a[mt], bl);
                }
            }
        }
    }

    // ---- writeback h as fp16 (one u32 = half2 per fragment pair) ----
    #pragma unroll
    for (int mt = 0; mt < 2; mt++) {
        int row0 = block_row + wm * 32 + mt * 16 + g;
        int row8 = row0 + 8;
        #pragma unroll
        for (int nt = 0; nt < 8; nt++) {
            int col = wn * 64 + nt * 8 + 2 * t;       // even
            if (row0 < M)
                hu[((size_t)row0 * F_OUT + col) >> 1] =
                    pack_h2(acc[mt][nt][0], acc[mt][nt][1]);
            if (row8 < M)
                hu[((size_t)row8 * F_OUT + col) >> 1] =
                    pack_h2(acc[mt][nt][2], acc[mt][nt][3]);
        }
    }
}

// ---------------------------------------------------------------------------
// Kernel 3: CSR aggregation — warp per dst node; fp16 h gather (uint2/lane),
// fp32 accumulation.
// ---------------------------------------------------------------------------
__global__ __launch_bounds__(256)
void aggregate_kernel(const __half* __restrict__ h16,
                      const float* __restrict__ bias,
                      float* __restrict__ out, int N) {
    const int warp = (blockIdx.x * blockDim.x + threadIdx.x) >> 5;
    const int lane = threadIdx.x & 31;
    if (warp >= N) return;

    const int s0 = g_off[warp];
    const int s1 = g_off[warp + 1];
    float4 acc = ((const float4*)bias)[lane];

    for (int base = s0; base < s1; base += 32) {
        int s = 0; float v = 0.0f;
        if (base + lane < s1) {
            int2 e = g_edge[base + lane];
            s = e.x;
            v = __int_as_float(e.y);
        }
        const int cnt = min(32, s1 - base);
        #pragma unroll 4
        for (int j = 0; j < cnt; j++) {
            int   ss = __shfl_sync(0xFFFFFFFFu, s, j);
            float vv = __shfl_sync(0xFFFFFFFFu, v, j);
            uint2 raw = ((const uint2*)(h16 + (size_t)ss * F_OUT))[lane];
            float2 f0 = __half22float2(*(const __half2*)&raw.x);
            float2 f1 = __half22float2(*(const __half2*)&raw.y);
            acc.x += f0.x * vv; acc.y += f0.y * vv;
            acc.z += f1.x * vv; acc.w += f1.y * vv;
        }
    }
    ((float4*)(out + (size_t)warp * F_OUT))[lane] = acc;
}

// ---------------------------------------------------------------------------
// Launch.  Inputs: x[f32], edge_src[i32], edge_dst[i32], edge_vals[f32],
//                  kernel[f32], bias[f32]
// CSR build forked onto a side stream, overlapped with wsplit+GEMM.
// ---------------------------------------------------------------------------
extern "C" void kernel_launch(void* const* d_in, const int* in_sizes, int n_in,
                              void* d_out, int out_size) {
    const float* x    = (const float*)d_in[0];
    const int*   esrc = (const int*)d_in[1];
    const int*   edst = (const int*)d_in[2];
    const float* eval = (const float*)d_in[3];
    const float* w    = (const float*)d_in[4];
    const float* bias = (const float*)d_in[5];
    float*       out  = (float*)d_out;

    const int M = in_sizes[0] / F_IN;     // 100000 nodes
    const int E = in_sizes[1];            // 1.6M edges
    const int n_pad  = ((M + SCAN_BLK - 1) / SCAN_BLK) * SCAN_BLK;
    const int n_sblk = n_pad / SCAN_BLK;  // 98

    __half *h16, *bh, *bl;
    cudaGetSymbolAddress((void**)&h16, g_h16);
    cudaGetSymbolAddress((void**)&bh,  g_Bh16);
    cudaGetSymbolAddress((void**)&bl,  g_Bl16);

    static cudaStream_t s2 = nullptr;
    static cudaEvent_t ev_fork = nullptr, ev_join = nullptr;
    static int init_done = 0;
    if (!init_done) {
        cudaStreamCreateWithFlags(&s2, cudaStreamNonBlocking);
        cudaEventCreateWithFlags(&ev_fork, cudaEventDisableTiming);
        cudaEventCreateWithFlags(&ev_join, cudaEventDisableTiming);
        cudaFuncSetAttribute(gemm_mma_kernel,
                             cudaFuncAttributeMaxDynamicSharedMemorySize,
                             GEMM_SMEM_BYTES);
        init_done = 1;
    }

    // ---- fork: CSR build on s2 ----
    cudaEventRecord(ev_fork, 0);
    cudaStreamWaitEvent(s2, ev_fork, 0);
    zero_cnt_kernel<<<(n_pad + 255) / 256, 256, 0, s2>>>(n_pad);
    count_kernel<<<(E + 255) / 256, 256, 0, s2>>>(edst, E);
    scanA_kernel<<<n_sblk, SCAN_BLK, 0, s2>>>();
    scanB_kernel<<<1, 256, 0, s2>>>(n_sblk);
    scanC_kernel<<<(M + 256) / 256, 256, 0, s2>>>(M, E);
    fill_kernel<<<(E + 255) / 256, 256, 0, s2>>>(edst, esrc, eval, E);
    cudaEventRecord(ev_join, s2);

    // ---- main stream: dense path ----
    wsplit_kernel<<<F_IN, F_OUT>>>(w, bh, bl);
    {
        int blocks = (M + 127) / 128;
        gemm_mma_kernel<<<blocks, 256, GEMM_SMEM_BYTES>>>(x, bh, bl, h16, M);
    }

    // ---- join, then aggregate ----
    cudaStreamWaitEvent(0, ev_join, 0);
    {
        int blocks = (M * 32 + 255) / 256;   // 12500
        aggregate_kernel<<<blocks, 256>>>(h16, bias, out, M);
    }
}

// round 10
// speedup vs baseline: 2.4805x; 1.0219x over previous
#include <cuda_runtime.h>
#include <cuda_fp16.h>
#include <cstdint>

#define F_IN     256
#define F_OUT    128
#define MAX_N    100352            // 98 * 1024, covers 100000
#define MAX_E    1600000
#define SCAN_BLK 1024

// Static scratch — __device__ globals (no allocation allowed).
__device__ __half g_h16[(size_t)100000 * F_OUT];  // h = x @ W, fp16 (25.6 MB)
__device__ __half g_Bh16[F_IN * F_OUT];           // W^T fp16, [n][k]
__device__ int   g_cnt[MAX_N];
__device__ int   g_scan[MAX_N];
__device__ int   g_bsum[256];
__device__ int   g_off[MAX_N + 1];
__device__ int   g_cur[MAX_N];
__device__ int2  g_edge[MAX_E];                   // (src, val_bits) CSR order

// ---------------------------------------------------------------------------
// CSR build: count -> scanA -> scanB -> scanC -> fill(packed)  (unchanged)
// ---------------------------------------------------------------------------
__global__ void zero_cnt_kernel(int n_pad) {
    int i = blockIdx.x * blockDim.x + threadIdx.x;
    if (i < n_pad) g_cnt[i] = 0;
}

__global__ void count_kernel(const int* __restrict__ edge_dst, int E) {
    int i = blockIdx.x * blockDim.x + threadIdx.x;
    if (i < E) atomicAdd(&g_cnt[edge_dst[i]], 1);
}

__global__ __launch_bounds__(SCAN_BLK)
void scanA_kernel() {
    __shared__ int s[SCAN_BLK];
    int t = threadIdx.x;
    int i = blockIdx.x * SCAN_BLK + t;
    int v = g_cnt[i];
    s[t] = v;
    __syncthreads();
    #pragma unroll
    for (int off = 1; off < SCAN_BLK; off <<= 1) {
        int tmp = (t >= off) ? s[t - off] : 0;
        __syncthreads();
        s[t] += tmp;
        __syncthreads();
    }
    g_scan[i] = s[t] - v;
    if (t == SCAN_BLK - 1) g_bsum[blockIdx.x] = s[t];
}

__global__ __launch_bounds__(256)
void scanB_kernel(int nblk) {
    __shared__ int s[256];
    int t = threadIdx.x;
    int v = (t < nblk) ? g_bsum[t] : 0;
    s[t] = v;
    __syncthreads();
    #pragma unroll
    for (int off = 1; off < 256; off <<= 1) {
        int tmp = (t >= off) ? s[t - off] : 0;
        __syncthreads();
        s[t] += tmp;
        __syncthreads();
    }
    g_bsum[t] = s[t] - v;
}

__global__ void scanC_kernel(int N, int E) {
    int i = blockIdx.x * blockDim.x + threadIdx.x;
    if (i <= N) {
        int o = (i == N) ? E : (g_scan[i] + g_bsum[i / SCAN_BLK]);
        g_off[i] = o;
        if (i < N) g_cur[i] = o;
    }
}

__global__ void fill_kernel(const int* __restrict__ edge_dst,
                            const int* __restrict__ edge_src,
                            const float* __restrict__ edge_vals, int E) {
    int i = blockIdx.x * blockDim.x + threadIdx.x;
    if (i < E) {
        int p = atomicAdd(&g_cur[edge_dst[i]], 1);
        g_edge[p] = make_int2(edge_src[i], __float_as_int(edge_vals[i]));
    }
}

// ---------------------------------------------------------------------------
// Kernel 2a: W transpose to fp16:  Bh[n][k] = fp16(w[k][n])
// ---------------------------------------------------------------------------
__global__ void wsplit_kernel(const float* __restrict__ w,
                              __half* __restrict__ bh) {
    int k = blockIdx.x;        // 0..255
    int n = threadIdx.x;       // 0..127
    bh[n * F_IN + k] = __float2half_rn(w[k * F_OUT + n]);
}

// ---------------------------------------------------------------------------
// Kernel 2b: mma.sync fp16 GEMM (single pass), h written as fp16.
// ---------------------------------------------------------------------------
#define KC       32
#define NCHUNK   (F_IN / KC)       // 8
#define ASU      20                // u32 per SMEM row (16 data + 4 pad)
#define SM_A     0
#define SM_BH    (128 * ASU)
#define GEMM_SMEM_BYTES (2 * 128 * ASU * 4)   // 20480

__device__ __forceinline__ uint32_t pack_h2(float a, float b) {
    __half2 t = __floats2half2_rn(a, b);   // .x = a (low half)
    return *(uint32_t*)&t;
}

__device__ __forceinline__ void mma_f16(float* d, const uint32_t* a,
                                        const uint32_t* b) {
    asm volatile(
        "mma.sync.aligned.m16n8k16.row.col.f32.f16.f16.f32 "
        "{%0, %1, %2, %3}, {%4, %5, %6, %7}, {%8, %9}, {%0, %1, %2, %3};"
        : "+f"(d[0]), "+f"(d[1]), "+f"(d[2]), "+f"(d[3])
        : "r"(a[0]), "r"(a[1]), "r"(a[2]), "r"(a[3]), "r"(b[0]), "r"(b[1]));
}

__global__ __launch_bounds__(256, 2)
void gemm_mma_kernel(const float* __restrict__ x,
                     const __half* __restrict__ bh_g,
                     __half* __restrict__ h16, int M) {
    extern __shared__ uint32_t smu[];
    const int tid  = threadIdx.x;
    const int wid  = tid >> 5;
    const int lane = tid & 31;
    const int g = lane >> 2;
    const int t = lane & 3;
    const int wm = wid & 3;
    const int wn = wid >> 2;
    const int block_row = blockIdx.x * 128;

    const uint32_t* bhu = (const uint32_t*)bh_g;   // [n][128] u32 rows
    uint32_t* hu = (uint32_t*)h16;                 // h as u32 (half2) words

    float acc[2][8][4];
    #pragma unroll
    for (int i = 0; i < 2; i++)
        #pragma unroll
        for (int j = 0; j < 8; j++)
            #pragma unroll
            for (int q = 0; q < 4; q++) acc[i][j][q] = 0.0f;

    for (int c = 0; c < NCHUNK; c++) {
        if (c > 0) __syncthreads();
        // ---- A: 128 rows x 32 k; fp32 -> fp16, packed u32 pairs ----
        #pragma unroll
        for (int i = 0; i < 4; i++) {
            int fidx = i * 256 + tid;          // 1024 float4 slots
            int row = fidx >> 3, c4 = fidx & 7;
            int grow = block_row + row;
            float4 v = make_float4(0.f, 0.f, 0.f, 0.f);
            if (grow < M)
                v = *(const float4*)(x + (size_t)grow * F_IN + c * KC + c4 * 4);
            uint32_t base = row * ASU + c4 * 2;
            *(uint2*)&smu[SM_A + base] =
                make_uint2(pack_h2(v.x, v.y), pack_h2(v.z, v.w));
        }
        // ---- B: 128 n-rows x 32 k (fp16 in gmem) ----
        {
            int fidx = tid;                    // 256 uint4 slots
            int row = fidx >> 1, q = fidx & 1;
            const size_t go = (size_t)row * (F_IN / 2) + c * (KC / 2) + q * 8;
            uint4 vh0 = *(const uint4*)(bhu + go);
            uint4 vh1 = *(const uint4*)(bhu + go + 4);
            uint32_t base = row * ASU + q * 8;
            *(uint4*)&smu[SM_BH + base] = vh0;
            *(uint4*)&smu[SM_BH + base + 4] = vh1;
        }
        __syncthreads();

        #pragma unroll
        for (int kp = 0; kp < KC / 2; kp += 8) {   // two k16 steps
            uint32_t a[2][4];
            #pragma unroll
            for (int mt = 0; mt < 2; mt++) {
                int r0 = (wm * 32 + mt * 16 + g) * ASU + kp + t;
                int r8 = (wm * 32 + mt * 16 + g + 8) * ASU + kp + t;
                a[mt][0] = smu[SM_A + r0];
                a[mt][1] = smu[SM_A + r8];
                a[mt][2] = smu[SM_A + r0 + 4];
                a[mt][3] = smu[SM_A + r8 + 4];
            }
            #pragma unroll
            for (int nt = 0; nt < 8; nt++) {
                int nrow = (wn * 64 + nt * 8 + g) * ASU + kp + t;
                uint32_t bh[2];
                bh[0] = smu[SM_BH + nrow];
                bh[1] = smu[SM_BH + nrow + 4];
                #pragma unroll
                for (int mt = 0; mt < 2; mt++)
                    mma_f16(acc[mt][nt], a[mt], bh);
            }
        }
    }

    // ---- writeback h as fp16 (one u32 = half2 per fragment pair) ----
    #pragma unroll
    for (int mt = 0; mt < 2; mt++) {
        int row0 = block_row + wm * 32 + mt * 16 + g;
        int row8 = row0 + 8;
        #pragma unroll
        for (int nt = 0; nt < 8; nt++) {
            int col = wn * 64 + nt * 8 + 2 * t;       // even
            if (row0 < M)
                hu[((size_t)row0 * F_OUT + col) >> 1] =
                    pack_h2(acc[mt][nt][0], acc[mt][nt][1]);
            if (row8 < M)
                hu[((size_t)row8 * F_OUT + col) >> 1] =
                    pack_h2(acc[mt][nt][2], acc[mt][nt][3]);
        }
    }
}

// ---------------------------------------------------------------------------
// Kernel 3: CSR aggregation — warp per dst node; 16 lanes per edge,
// 2 edges per step (uint4 = 8 halves per lane); fp32 accumulation.
// ---------------------------------------------------------------------------
__global__ __launch_bounds__(256)
void aggregate_kernel(const __half* __restrict__ h16,
                      const float* __restrict__ bias,
                      float* __restrict__ out, int N) {
    const int warp = (blockIdx.x * blockDim.x + threadIdx.x) >> 5;
    const int lane = threadIdx.x & 31;
    const int half = lane >> 4;        // 0/1: which edge of the pair
    const int sub  = lane & 15;        // feature chunk: cols [sub*8, sub*8+8)
    if (warp >= N) return;

    const int s0 = g_off[warp];
    const int s1 = g_off[warp + 1];

    float acc[8];
    #pragma unroll
    for (int q = 0; q < 8; q++) acc[q] = 0.0f;

    for (int base = s0; base < s1; base += 32) {
        int s = 0; float v = 0.0f;
        if (base + lane < s1) {
            int2 e = g_edge[base + lane];
            s = e.x;
            v = __int_as_float(e.y);
        }
        const int cnt = min(32, s1 - base);
        #pragma unroll 4
        for (int j = 0; j < cnt; j += 2) {
            const int idx = j + half;                      // <= 31; v=0 pads
            int   ss = __shfl_sync(0xFFFFFFFFu, s, idx);
            float vv = __shfl_sync(0xFFFFFFFFu, v, idx);
            uint4 raw = ((const uint4*)(h16 + (size_t)ss * F_OUT))[sub];
            float2 f0 = __half22float2(*(const __half2*)&raw.x);
            float2 f1 = __half22float2(*(const __half2*)&raw.y);
            float2 f2 = __half22float2(*(const __half2*)&raw.z);
            float2 f3 = __half22float2(*(const __half2*)&raw.w);
            acc[0] += f0.x * vv; acc[1] += f0.y * vv;
            acc[2] += f1.x * vv; acc[3] += f1.y * vv;
            acc[4] += f2.x * vv; acc[5] += f2.y * vv;
            acc[6] += f3.x * vv; acc[7] += f3.y * vv;
        }
    }

    // combine the two edge-parity halves: lanes i and i+16 share columns
    #pragma unroll
    for (int q = 0; q < 8; q++)
        acc[q] += __shfl_xor_sync(0xFFFFFFFFu, acc[q], 16);

    if (half == 0) {
        const float4 b0 = ((const float4*)bias)[sub * 2];
        const float4 b1 = ((const float4*)bias)[sub * 2 + 1];
        float* op = out + (size_t)warp * F_OUT + sub * 8;
        *(float4*)op = make_float4(acc[0] + b0.x, acc[1] + b0.y,
                                   acc[2] + b0.z, acc[3] + b0.w);
        *(float4*)(op + 4) = make_float4(acc[4] + b1.x, acc[5] + b1.y,
                                         acc[6] + b1.z, acc[7] + b1.w);
    }
}

// ---------------------------------------------------------------------------
// Launch.  Inputs: x[f32], edge_src[i32], edge_dst[i32], edge_vals[f32],
//                  kernel[f32], bias[f32]
// CSR build forked onto a side stream, overlapped with wsplit+GEMM.
// ---------------------------------------------------------------------------
extern "C" void kernel_launch(void* const* d_in, const int* in_sizes, int n_in,
                              void* d_out, int out_size) {
    const float* x    = (const float*)d_in[0];
    const int*   esrc = (const int*)d_in[1];
    const int*   edst = (const int*)d_in[2];
    const float* eval = (const float*)d_in[3];
    const float* w    = (const float*)d_in[4];
    const float* bias = (const float*)d_in[5];
    float*       out  = (float*)d_out;

    const int M = in_sizes[0] / F_IN;     // 100000 nodes
    const int E = in_sizes[1];            // 1.6M edges
    const int n_pad  = ((M + SCAN_BLK - 1) / SCAN_BLK) * SCAN_BLK;
    const int n_sblk = n_pad / SCAN_BLK;  // 98

    __half *h16, *bh;
    cudaGetSymbolAddress((void**)&h16, g_h16);
    cudaGetSymbolAddress((void**)&bh,  g_Bh16);

    static cudaStream_t s2 = nullptr;
    static cudaEvent_t ev_fork = nullptr, ev_join = nullptr;
    static int init_done = 0;
    if (!init_done) {
        cudaStreamCreateWithFlags(&s2, cudaStreamNonBlocking);
        cudaEventCreateWithFlags(&ev_fork, cudaEventDisableTiming);
        cudaEventCreateWithFlags(&ev_join, cudaEventDisableTiming);
        cudaFuncSetAttribute(gemm_mma_kernel,
                             cudaFuncAttributeMaxDynamicSharedMemorySize,
                             GEMM_SMEM_BYTES);
        init_done = 1;
    }

    // ---- fork: CSR build on s2 ----
    cudaEventRecord(ev_fork, 0);
    cudaStreamWaitEvent(s2, ev_fork, 0);
    zero_cnt_kernel<<<(n_pad + 255) / 256, 256, 0, s2>>>(n_pad);
    count_kernel<<<(E + 255) / 256, 256, 0, s2>>>(edst, E);
    scanA_kernel<<<n_sblk, SCAN_BLK, 0, s2>>>();
    scanB_kernel<<<1, 256, 0, s2>>>(n_sblk);
    scanC_kernel<<<(M + 256) / 256, 256, 0, s2>>>(M, E);
    fill_kernel<<<(E + 255) / 256, 256, 0, s2>>>(edst, esrc, eval, E);
    cudaEventRecord(ev_join, s2);

    // ---- main stream: dense path ----
    wsplit_kernel<<<F_IN, F_OUT>>>(w, bh);
    {
        int blocks = (M + 127) / 128;
        gemm_mma_kernel<<<blocks, 256, GEMM_SMEM_BYTES>>>(x, bh, h16, M);
    }

    // ---- join, then aggregate ----
    cudaStreamWaitEvent(0, ev_join, 0);
    {
        int blocks = (M * 32 + 255) / 256;   // 12500
        aggregate_kernel<<<blocks, 256>>>(h16, bias, out, M);
    }
}